// round 10
// baseline (speedup 1.0000x reference)
#include <cuda_runtime.h>
#include <cuda_bf16.h>
#include <cstdint>

#define NN 20000
#define NE 400000
#define H  256

// ------- static scratch (allocations forbidden) -------
__device__ float    g_a[2][NN*H];
__device__ float    g_c[2][NN*H];
__device__ unsigned g_segout[2][NN*H];   // mapped-uint running max, 0 = empty
__device__ float    g_xw[2][NN*128];
__device__ float    g_h2[NN*256];
__device__ int      g_deg[2][NN];
__device__ int      g_offs[2][NN+1];
__device__ int      g_cursor[2][NN];
__device__ int      g_ssrc[2][NE];
__device__ int      g_sdst[2][NE];
__device__ float    g_dinv[2][NN];
__device__ float    g_partial[1024*3];
__device__ unsigned char g_w2q1[2][H*H]; // int8 hi digit of W2^T, [n][k]
__device__ unsigned char g_w2q2[2][H*H]; // int8 lo digit
__device__ float    g_wsc[2][4*256];     // scale per [chunk][n]
__device__ float    g_winv[2][4*256];

__device__ __forceinline__ unsigned fmap(float f) {
    unsigned b = __float_as_uint(f);
    return b ^ ((unsigned)((int)b >> 31) | 0x80000000u);
}
__device__ __forceinline__ uint32_t smem_u32(const void* p) {
    uint32_t a;
    asm("{ .reg .u64 t; cvta.to.shared.u64 t, %1; cvt.u32.u64 %0, t; }" : "=r"(a) : "l"(p));
    return a;
}
__device__ __forceinline__ void mma_s8(int* c, const uint32_t* a,
                                       uint32_t b0, uint32_t b1) {
    asm("mma.sync.aligned.m16n8k32.row.col.s32.s8.s8.s32 "
        "{%0,%1,%2,%3}, {%4,%5,%6,%7}, {%8,%9}, {%0,%1,%2,%3};"
        : "+r"(c[0]), "+r"(c[1]), "+r"(c[2]), "+r"(c[3])
        : "r"(a[0]), "r"(a[1]), "r"(a[2]), "r"(a[3]), "r"(b0), "r"(b1));
}
__device__ __forceinline__ void ldsm4(uint32_t* r, uint32_t addr) {
    asm volatile("ldmatrix.sync.aligned.m8n8.x4.shared.b16 {%0,%1,%2,%3}, [%4];"
        : "=r"(r[0]), "=r"(r[1]), "=r"(r[2]), "=r"(r[3]) : "r"(addr));
}

// ------- small prep kernels -------
__global__ void init_kernel() {
    int idx = blockIdx.x * 256 + threadIdx.x;
    if (idx < 2*NN*H) (&g_segout[0][0])[idx] = 0u;
    if (idx < 2*NN)   (&g_deg[0][0])[idx] = 0;
}

__global__ void uv_kernel(const float* __restrict__ pos, const float* __restrict__ W1,
                          const float* __restrict__ bias1, int g) {
    int i = blockIdx.x, ch = threadIdx.x;
    float p0 = pos[i*3+0], p1 = pos[i*3+1], p2 = pos[i*3+2];
    float c = p0*W1[3*H+ch] + p1*W1[4*H+ch] + p2*W1[5*H+ch];
    float a = p0*W1[0*H+ch] + p1*W1[1*H+ch] + p2*W1[2*H+ch] + c + bias1[ch];
    g_a[g][i*H+ch] = a;
    g_c[g][i*H+ch] = c;
}

// per (chunk, n): scale = colmax/127 over 64 k
__global__ void w2max_kernel(const float* __restrict__ W2, int g) {
    int idx = blockIdx.x * 256 + threadIdx.x;
    if (idx >= 1024) return;
    int ck = idx >> 8, n = idx & 255;
    float m = 0.f;
    for (int j = 0; j < 64; j++) m = fmaxf(m, fabsf(W2[(ck*64 + j)*256 + n]));
    g_wsc[g][idx]  = m * (1.f/127.f);
    g_winv[g][idx] = (m > 0.f) ? 127.f/m : 0.f;
}

// quantize W2^T to two int8 digits, layout [n][k]
__global__ void w2quant_kernel(const float* __restrict__ W2, int g) {
    int idx = blockIdx.x * 256 + threadIdx.x;  // n*256 + k
    int n = idx >> 8, k = idx & 255;
    int ck = k >> 6;
    float w = W2[k*256 + n] * g_winv[g][ck*256 + n];
    float f1 = rintf(w);
    float f2 = rintf((w - f1) * 254.f);
    g_w2q1[g][idx] = (unsigned char)(int)f1;
    g_w2q2[g][idx] = (unsigned char)(int)f2;
}

__global__ void deg_kernel(const int* __restrict__ ei, int g) {
    int e = blockIdx.x * 256 + threadIdx.x;
    if (e < NE) atomicAdd(&g_deg[g][ei[NE + e]], 1);
}

__global__ void scan_kernel(int g) {
    __shared__ int ss[1024];
    int t = threadIdx.x;
    const int CH = (NN + 1023) / 1024;
    int beg = t * CH, end = beg + CH;
    if (end > NN) end = NN;
    if (beg > NN) beg = NN;
    int s = 0;
    for (int i = beg; i < end; i++) s += g_deg[g][i];
    ss[t] = s;
    __syncthreads();
    for (int off = 1; off < 1024; off <<= 1) {
        int v = (t >= off) ? ss[t-off] : 0;
        __syncthreads();
        ss[t] += v;
        __syncthreads();
    }
    int run = (t == 0) ? 0 : ss[t-1];
    for (int i = beg; i < end; i++) {
        g_offs[g][i] = run; g_cursor[g][i] = run; run += g_deg[g][i];
    }
    if (t == 1023) g_offs[g][NN] = NE;
}

__global__ void dinv_kernel() {
    int idx = blockIdx.x * 256 + threadIdx.x;
    if (idx < 2*NN) {
        int g = idx / NN, i = idx - g*NN;
        g_dinv[g][i] = rsqrtf(1.f + (float)g_deg[g][i]);
    }
}

__global__ void fill_kernel(const int* __restrict__ ei, int g) {
    int e = blockIdx.x * 256 + threadIdx.x;
    if (e < NE) {
        int d = ei[NE + e];
        int p = atomicAdd(&g_cursor[g][d], 1);
        g_ssrc[g][p] = ei[e];
        g_sdst[g][p] = d;
    }
}

// ------- int8 IMMA pointnet: 128 sorted edges x 256 ch -------
// smem pitch 80 bytes per 64-byte s8 row (conflict-free ldmatrix)
// OFF_DST must sit ABOVE the epilogue buf region (128*257*4 = 131584 bytes)
#define OFF_A1 0
#define OFF_A2 10240
#define OFF_W1 20480
#define OFF_W2 40960
#define OFF_SA 61440
#define OFF_SW 61952
#define OFF_DST 131584
#define PN_SMEM 132096
#define INV254 (1.f/254.f)

__global__ __launch_bounds__(512, 1)
void pointnet_imma(const float* __restrict__ b2, int g) {
    extern __shared__ char AB[];
    uint32_t abu = smem_u32(AB);
    int tid = threadIdx.x, lane = tid & 31, wid = tid >> 5;
    int e0 = blockIdx.x * 128;
    int* s_dst = (int*)(AB + OFF_DST);
    float* sSA = (float*)(AB + OFF_SA);
    float* sSW = (float*)(AB + OFF_SW);
    if (tid < 128) s_dst[tid] = g_sdst[g][e0 + tid];

    // gather assignment: edge row = tid>>2, 16-k quarter = (tid&3)*16
    int ge = tid >> 2, kq = (tid & 3) * 16;
    int esrc = g_ssrc[g][e0 + ge] * 256;
    int edst = g_sdst[g][e0 + ge] * 256;
    const float* __restrict__ Aa = g_a[g];
    const float* __restrict__ Cc = g_c[g];
    const unsigned char* __restrict__ wq1 = g_w2q1[g];
    const unsigned char* __restrict__ wq2 = g_w2q2[g];

    // warp tiling: 4 edge-groups x 4 ch-groups; warp tile 32 edges x 64 ch
    int eg = wid >> 2, cg = wid & 3;
    int qrow = lane >> 2;
    int qc = (lane & 3) * 2;

    uint32_t aQ1 = abu + OFF_A1 + (uint32_t)(eg*32 + (lane & 15))*80 + (lane >> 4)*16;
    uint32_t aQ2 = aQ1 + (OFF_A2 - OFF_A1);
    uint32_t bQ1 = abu + OFF_W1 +
        (uint32_t)(cg*64 + (lane >> 4)*8 + (lane & 7))*80 + ((lane >> 3) & 1)*16;
    uint32_t bQ2 = bQ1 + (OFF_W2 - OFF_W1);

    float out[2][8][4];
#pragma unroll
    for (int mt = 0; mt < 2; mt++)
#pragma unroll
        for (int nt = 0; nt < 8; nt++)
#pragma unroll
            for (int j = 0; j < 4; j++) out[mt][nt][j] = 0.f;

    for (int ck = 0; ck < 4; ck++) {
        // ---- gather + relu + int8 two-digit quantize ----
        {
            int k0 = ck*64 + kq;
            float h[16];
#pragma unroll
            for (int q = 0; q < 4; q++) {
                float4 av = *(const float4*)(Aa + esrc + k0 + q*4);
                float4 cv = *(const float4*)(Cc + edst + k0 + q*4);
                h[4*q+0] = fmaxf(av.x - cv.x, 0.f);
                h[4*q+1] = fmaxf(av.y - cv.y, 0.f);
                h[4*q+2] = fmaxf(av.z - cv.z, 0.f);
                h[4*q+3] = fmaxf(av.w - cv.w, 0.f);
            }
            float m = h[0];
#pragma unroll
            for (int j = 1; j < 16; j++) m = fmaxf(m, h[j]);
            m = fmaxf(m, __shfl_xor_sync(0xffffffffu, m, 1));
            m = fmaxf(m, __shfl_xor_sync(0xffffffffu, m, 2));
            float inv = (m > 0.f) ? 127.f/m : 0.f;
            uint32_t pk1[4], pk2[4];
#pragma unroll
            for (int q = 0; q < 4; q++) {
                uint32_t u1 = 0, u2 = 0;
#pragma unroll
                for (int j = 0; j < 4; j++) {
                    float qv = h[4*q+j] * inv;
                    float f1 = rintf(qv);
                    float f2 = rintf((qv - f1) * 254.f);
                    u1 |= ((uint32_t)(int)f1 & 255u) << (8*j);
                    u2 |= ((uint32_t)(int)f2 & 255u) << (8*j);
                }
                pk1[q] = u1; pk2[q] = u2;
            }
            *(uint4*)(AB + OFF_A1 + ge*80 + kq) = make_uint4(pk1[0], pk1[1], pk1[2], pk1[3]);
            *(uint4*)(AB + OFF_A2 + ge*80 + kq) = make_uint4(pk2[0], pk2[1], pk2[2], pk2[3]);
            if ((tid & 3) == 0) sSA[ge] = m * (1.f/127.f);
        }
        // ---- stream quantized W chunk [n][64] (both digits) ----
        {
#pragma unroll
            for (int i = 0; i < 2; i++) {
                int idx = tid + i*512;              // 1024 units of 16B per digit
                int n = idx >> 2, q = idx & 3;
                *(uint4*)(AB + OFF_W1 + n*80 + q*16) =
                    *(const uint4*)(wq1 + n*256 + ck*64 + q*16);
                *(uint4*)(AB + OFF_W2 + n*80 + q*16) =
                    *(const uint4*)(wq2 + n*256 + ck*64 + q*16);
            }
            if (tid < 256) sSW[tid] = g_wsc[g][ck*256 + tid];
        }
        __syncthreads();

        // ---- IMMA: 2 k32 steps per chunk, 3 products, per-chunk rescale ----
#pragma unroll
        for (int p = 0; p < 4; p++) {
            uint32_t w1a[4], w1b[4], w2a[4], w2b[4];
            ldsm4(w1a, bQ1 + p*1280);
            ldsm4(w1b, bQ1 + p*1280 + 32);
            ldsm4(w2a, bQ2 + p*1280);
            ldsm4(w2b, bQ2 + p*1280 + 32);
            float sw0a = sSW[cg*64 + p*16 + qc];
            float sw0b = sSW[cg*64 + p*16 + qc + 1];
            float sw1a = sSW[cg*64 + p*16 + 8 + qc];
            float sw1b = sSW[cg*64 + p*16 + 8 + qc + 1];
#pragma unroll
            for (int mt = 0; mt < 2; mt++) {
                int c11[2][4], cm[2][4];
#pragma unroll
                for (int t = 0; t < 2; t++)
#pragma unroll
                    for (int j = 0; j < 4; j++) { c11[t][j] = 0; cm[t][j] = 0; }
                uint32_t a1[4], a2[4];
                ldsm4(a1, aQ1 + mt*1280);
                ldsm4(a2, aQ2 + mt*1280);
                mma_s8(c11[0], a1, w1a[0], w1a[1]);
                mma_s8(c11[1], a1, w1a[2], w1a[3]);
                mma_s8(cm[0],  a1, w2a[0], w2a[1]);
                mma_s8(cm[0],  a2, w1a[0], w1a[1]);
                mma_s8(cm[1],  a1, w2a[2], w2a[3]);
                mma_s8(cm[1],  a2, w1a[2], w1a[3]);
                uint32_t a1s[4], a2s[4];
                ldsm4(a1s, aQ1 + mt*1280 + 32);
                ldsm4(a2s, aQ2 + mt*1280 + 32);
                mma_s8(c11[0], a1s, w1b[0], w1b[1]);
                mma_s8(c11[1], a1s, w1b[2], w1b[3]);
                mma_s8(cm[0],  a1s, w2b[0], w2b[1]);
                mma_s8(cm[0],  a2s, w1b[0], w1b[1]);
                mma_s8(cm[1],  a1s, w2b[2], w2b[3]);
                mma_s8(cm[1],  a2s, w1b[2], w1b[3]);
                // rescale into f32 output
                float sa0 = sSA[eg*32 + mt*16 + qrow];
                float sa1 = sSA[eg*32 + mt*16 + qrow + 8];
#pragma unroll
                for (int t = 0; t < 2; t++) {
                    float swa = (t == 0) ? sw0a : sw1a;
                    float swb = (t == 0) ? sw0b : sw1b;
                    out[mt][2*p+t][0] += sa0*swa*((float)c11[t][0] + (float)cm[t][0]*INV254);
                    out[mt][2*p+t][1] += sa0*swb*((float)c11[t][1] + (float)cm[t][1]*INV254);
                    out[mt][2*p+t][2] += sa1*swa*((float)c11[t][2] + (float)cm[t][2]*INV254);
                    out[mt][2*p+t][3] += sa1*swb*((float)c11[t][3] + (float)cm[t][3]*INV254);
                }
            }
        }
        __syncthreads();
    }

    // ---- epilogue: out -> SMEM buf[128][257] -> segmented max -> atomics ----
    float* buf = (float*)AB;
#pragma unroll
    for (int mt = 0; mt < 2; mt++) {
        int row = eg*32 + mt*16 + qrow;
#pragma unroll
        for (int nt = 0; nt < 8; nt++) {
            int col = cg*64 + nt*8 + qc;
            buf[row*257 + col]       = out[mt][nt][0];
            buf[row*257 + col + 1]   = out[mt][nt][1];
            buf[(row+8)*257 + col]   = out[mt][nt][2];
            buf[(row+8)*257 + col+1] = out[mt][nt][3];
        }
    }
    __syncthreads();
    {
        unsigned* __restrict__ seg = &g_segout[g][0];
        int gch = tid & 255;
        int ebase = (tid >> 8) * 64;
        float bias = b2[gch];
        int cur = s_dst[ebase];
        float mx = buf[ebase*257 + gch];
        for (int q = 1; q < 64; q++) {
            int d = s_dst[ebase + q];
            float v = buf[(ebase+q)*257 + gch];
            if (d != cur) {
                atomicMax(&seg[cur*256 + gch], fmap(mx + bias));
                cur = d; mx = v;
            } else mx = fmaxf(mx, v);
        }
        atomicMax(&seg[cur*256 + gch], fmap(mx + bias));
    }
}

// ------- xw = decode(segout) @ gW : [N,512]@[512,128], decode fused -------
__global__ __launch_bounds__(256)
void xw_kernel(const float* __restrict__ Wg, int g) {
    __shared__ float s_a[64*16];
    __shared__ float4 s_b[16*32];
    int tid = threadIdx.x, tx = tid & 31, ty = tid >> 5;
    int row0 = blockIdx.x * 64;
    float acc[8][4];
#pragma unroll
    for (int i = 0; i < 8; i++)
#pragma unroll
        for (int j = 0; j < 4; j++) acc[i][j] = 0.f;
    int lr = tid >> 2, lk = (tid & 3) * 4;
    int ar = row0 + lr; if (ar > NN-1) ar = NN-1;
    const float4* B4 = (const float4*)Wg;
    for (int k0 = 0; k0 < 512; k0 += 16) {
        int kk0 = k0 + lk;
        const unsigned* sp = (kk0 < 256) ? &g_segout[0][ar*256 + kk0]
                                         : &g_segout[1][ar*256 + kk0 - 256];
        uint4 u = *(const uint4*)sp;
        float4 av;
        av.x = (u.x > 0x80000000u) ? __uint_as_float(u.x ^ 0x80000000u) : 0.f;
        av.y = (u.y > 0x80000000u) ? __uint_as_float(u.y ^ 0x80000000u) : 0.f;
        av.z = (u.z > 0x80000000u) ? __uint_as_float(u.z ^ 0x80000000u) : 0.f;
        av.w = (u.w > 0x80000000u) ? __uint_as_float(u.w ^ 0x80000000u) : 0.f;
        float4 bv[2];
#pragma unroll
        for (int q = 0; q < 2; q++) {
            int idx = tid + q*256;
            bv[q] = B4[(k0 + (idx >> 5))*32 + (idx & 31)];
        }
        __syncthreads();
        *(float4*)(s_a + lr*16 + lk) = av;
#pragma unroll
        for (int q = 0; q < 2; q++) s_b[tid + q*256] = bv[q];
        __syncthreads();
#pragma unroll
        for (int kk = 0; kk < 16; kk++) {
            float4 b = s_b[kk*32 + tx];
#pragma unroll
            for (int i = 0; i < 8; i++) {
                float a = s_a[(ty*8 + i)*16 + kk];
                acc[i][0] += a*b.x; acc[i][1] += a*b.y;
                acc[i][2] += a*b.z; acc[i][3] += a*b.w;
            }
        }
    }
#pragma unroll
    for (int i = 0; i < 8; i++) {
        int r = row0 + ty*8 + i;
        if (r < NN)
            *(float4*)(g_xw[g] + r*128 + tx*4) =
                make_float4(acc[i][0], acc[i][1], acc[i][2], acc[i][3]);
    }
}

__global__ void agg_kernel(const float* __restrict__ bias, int g) {
    int i = blockIdx.x, ch = threadIdx.x;
    const float* __restrict__ xw = g_xw[g];
    float di = g_dinv[g][i];
    int beg = g_offs[g][i], end = g_offs[g][i+1];
    float acc = 0.f;
    for (int e = beg; e < end; e++) {
        int s = g_ssrc[g][e];
        acc += xw[s*128 + ch] * g_dinv[g][s];
    }
    float v = di*acc + xw[i*128 + ch]*di*di + bias[ch];
    g_h2[i*256 + g*128 + ch] = fmaxf(v, 0.f);
}

__global__ __launch_bounds__(256)
void c3cls_kernel(const float* __restrict__ Wc, const float* __restrict__ bc,
                  const float* __restrict__ clsW) {
    __shared__ float s_a[64*16];
    __shared__ float4 s_b[16*32];
    __shared__ float red[256];
    int tid = threadIdx.x, tx = tid & 31, ty = tid >> 5;
    int row0 = blockIdx.x * 64;
    float acc[8][4];
#pragma unroll
    for (int i = 0; i < 8; i++)
#pragma unroll
        for (int j = 0; j < 4; j++) acc[i][j] = 0.f;
    int lr = tid >> 2, lk = (tid & 3) * 4;
    int ar = row0 + lr; if (ar > NN-1) ar = NN-1;
    const float4* B4 = (const float4*)Wc;
    for (int k0 = 0; k0 < 256; k0 += 16) {
        float4 av = *(const float4*)(g_h2 + ar*256 + k0 + lk);
        float4 bv[2];
#pragma unroll
        for (int q = 0; q < 2; q++) {
            int idx = tid + q*256;
            bv[q] = B4[(k0 + (idx >> 5))*32 + (idx & 31)];
        }
        __syncthreads();
        *(float4*)(s_a + lr*16 + lk) = av;
#pragma unroll
        for (int q = 0; q < 2; q++) s_b[tid + q*256] = bv[q];
        __syncthreads();
#pragma unroll
        for (int kk = 0; kk < 16; kk++) {
            float4 b = s_b[kk*32 + tx];
#pragma unroll
            for (int i = 0; i < 8; i++) {
                float a = s_a[(ty*8 + i)*16 + kk];
                acc[i][0] += a*b.x; acc[i][1] += a*b.y;
                acc[i][2] += a*b.z; acc[i][3] += a*b.w;
            }
        }
    }
    float sum0 = 0.f, sum1 = 0.f, sum2 = 0.f;
#pragma unroll
    for (int i = 0; i < 8; i++) {
        int r = row0 + ty*8 + i;
        if (r < NN) {
#pragma unroll
            for (int jj = 0; jj < 4; jj++) {
                float v = fmaxf(acc[i][jj] + bc[tx*4 + jj], 0.f);
                const float* w = clsW + (r*128 + tx*4 + jj)*3;
                sum0 += v*w[0]; sum1 += v*w[1]; sum2 += v*w[2];
            }
        }
    }
    float sums[3] = {sum0, sum1, sum2};
#pragma unroll
    for (int r3 = 0; r3 < 3; r3++) {
        red[tid] = sums[r3];
        __syncthreads();
        for (int s = 128; s > 0; s >>= 1) {
            if (tid < s) red[tid] += red[tid + s];
            __syncthreads();
        }
        if (tid == 0) g_partial[blockIdx.x*3 + r3] = red[0];
        __syncthreads();
    }
}

__global__ void final_kernel(const float* __restrict__ clsb, float* __restrict__ out, int nblk) {
    int r = threadIdx.x;
    if (r < 3) {
        double s = (double)clsb[r];
        for (int i = 0; i < nblk; i++) s += (double)g_partial[i*3 + r];
        out[r] = (float)s;
    }
}

extern "C" void kernel_launch(void* const* d_in, const int* in_sizes, int n_in,
                              void* d_out, int out_size) {
    const float *pos[2]={0,0}, *W1[2]={0,0}, *b1[2]={0,0}, *W2[2]={0,0}, *b2[2]={0,0};
    const float *gW[2]={0,0}, *gb[2]={0,0}, *cW=0, *cb=0, *clsW=0, *clsb=0;
    const int *ei[2]={0,0};
    int npos=0, nei=0, nw1=0, n256=0, n64k=0, n128=0;
    for (int i = 0; i < n_in; i++) {
        int sz = in_sizes[i];
        const float* f = (const float*)d_in[i];
        if (sz == 3*NN)            { if (npos<2) pos[npos++] = f; }
        else if (sz == 2*NE)       { if (nei<2)  ei[nei++] = (const int*)d_in[i]; }
        else if (sz == 6*H)        { if (nw1<2)  W1[nw1++] = f; }
        else if (sz == H)          { int j=n256++; if(j==0)b1[0]=f; else if(j==1)b2[0]=f;
                                     else if(j==2)b1[1]=f; else if(j==3)b2[1]=f; }
        else if (sz == H*H)        { int j=n64k++; if(j<2) W2[j]=f; else if(j<4) gW[j-2]=f; }
        else if (sz == H/2)        { int j=n128++; if(j<2) gb[j]=f; else cb=f; }
        else if (sz == H*(H/2))    { cW = f; }
        else if (sz == NN*(H/2)*3) { clsW = f; }
        else if (sz == 3)          { clsb = f; }
    }

    static bool attr_done = false;
    if (!attr_done) {
        cudaFuncSetAttribute(pointnet_imma, cudaFuncAttributeMaxDynamicSharedMemorySize, PN_SMEM);
        attr_done = true;
    }

    init_kernel<<<(2*NN*H + 255)/256, 256>>>();
    for (int g = 0; g < 2; g++) {
        uv_kernel<<<NN, 256>>>(pos[g], W1[g], b1[g], g);
        w2max_kernel<<<4, 256>>>(W2[g], g);
        deg_kernel<<<(NE + 255)/256, 256>>>(ei[g], g);
    }
    for (int g = 0; g < 2; g++) {
        w2quant_kernel<<<256, 256>>>(W2[g], g);
        scan_kernel<<<1, 1024>>>(g);
        fill_kernel<<<(NE + 255)/256, 256>>>(ei[g], g);
    }
    dinv_kernel<<<(2*NN + 255)/256, 256>>>();
    for (int g = 0; g < 2; g++)
        pointnet_imma<<<NE/128, 512, PN_SMEM>>>(b2[g], g);
    for (int g = 0; g < 2; g++)
        xw_kernel<<<(NN + 63)/64, 256>>>(gW[g], g);
    for (int g = 0; g < 2; g++)
        agg_kernel<<<NN, 128>>>(gb[g], g);
    int nblk = (NN + 63)/64;
    c3cls_kernel<<<nblk, 256>>>(cW, cb, clsW);
    final_kernel<<<1, 32>>>(clsb, (float*)d_out, nblk);
}

// round 11
// speedup vs baseline: 2.4470x; 2.4470x over previous
#include <cuda_runtime.h>
#include <cuda_bf16.h>
#include <cstdint>

#define NN 20000
#define NE 400000
#define H  256

// ------- static scratch (allocations forbidden) -------
__device__ float    g_a[2][NN*H];
__device__ float    g_c[2][NN*H];
__device__ unsigned g_segout[2][NN*H];   // mapped-uint running max, 0 = empty
__device__ float    g_xw[2][NN*128];
__device__ float    g_h2[NN*256];
__device__ int      g_deg[2][NN];
__device__ int      g_offs[2][NN+1];
__device__ int      g_cursor[2][NN];
__device__ int      g_ssrc[2][NE];
__device__ int      g_sdst[2][NE];
__device__ float    g_dinv[2][NN];
__device__ float    g_partial[1024*3];
__device__ unsigned short g_w2h[2][H*H]; // bf16 hi of W2^T, [chunk][n][64k]
__device__ unsigned short g_w2l[2][H*H]; // bf16 lo

__device__ __forceinline__ unsigned fmap(float f) {
    unsigned b = __float_as_uint(f);
    return b ^ ((unsigned)((int)b >> 31) | 0x80000000u);
}
__device__ __forceinline__ uint32_t smem_u32(const void* p) {
    uint32_t a;
    asm("{ .reg .u64 t; cvta.to.shared.u64 t, %1; cvt.u32.u64 %0, t; }" : "=r"(a) : "l"(p));
    return a;
}
__device__ __forceinline__ void mma_bf16(float* c, const uint32_t* a,
                                         uint32_t b0, uint32_t b1) {
    asm("mma.sync.aligned.m16n8k16.row.col.f32.bf16.bf16.f32 "
        "{%0,%1,%2,%3}, {%4,%5,%6,%7}, {%8,%9}, {%0,%1,%2,%3};"
        : "+f"(c[0]), "+f"(c[1]), "+f"(c[2]), "+f"(c[3])
        : "r"(a[0]), "r"(a[1]), "r"(a[2]), "r"(a[3]), "r"(b0), "r"(b1));
}
__device__ __forceinline__ void ldsm4(uint32_t* r, uint32_t addr) {
    asm volatile("ldmatrix.sync.aligned.m8n8.x4.shared.b16 {%0,%1,%2,%3}, [%4];"
        : "=r"(r[0]), "=r"(r[1]), "=r"(r[2]), "=r"(r[3]) : "r"(addr));
}

// ------- fused prep kernels -------
__global__ void init_kernel() {
    int idx = blockIdx.x * 256 + threadIdx.x;
    if (idx < 2*NN*H) (&g_segout[0][0])[idx] = 0u;
    if (idx < 2*NN)   (&g_deg[0][0])[idx] = 0;
}

__global__ void uv_fused(const float* __restrict__ pos0, const float* __restrict__ pos1,
                         const float* __restrict__ W10, const float* __restrict__ W11,
                         const float* __restrict__ b10, const float* __restrict__ b11) {
    int g = blockIdx.x / NN, i = blockIdx.x - g*NN, ch = threadIdx.x;
    const float* pos = g ? pos1 : pos0;
    const float* W1  = g ? W11 : W10;
    const float* bb  = g ? b11 : b10;
    float p0 = pos[i*3+0], p1 = pos[i*3+1], p2 = pos[i*3+2];
    float c = p0*W1[3*H+ch] + p1*W1[4*H+ch] + p2*W1[5*H+ch];
    float a = p0*W1[0*H+ch] + p1*W1[1*H+ch] + p2*W1[2*H+ch] + c + bb[ch];
    g_a[g][i*H+ch] = a;
    g_c[g][i*H+ch] = c;
}

// W2 bf16 split, transposed to [n][k], chunked over k by 64; both graphs
__global__ void w2prep_fused(const float* __restrict__ W20, const float* __restrict__ W21) {
    int g = blockIdx.x >> 8;
    int idx = (blockIdx.x & 255) * 256 + threadIdx.x;  // k*256+n
    int k = idx >> 8, n = idx & 255;
    float w = (g ? W21 : W20)[idx];
    __nv_bfloat16 hb = __float2bfloat16(w);
    float hf = __bfloat162float(hb);
    __nv_bfloat16 lb = __float2bfloat16(w - hf);
    int o = (k >> 6)*16384 + n*64 + (k & 63);
    g_w2h[g][o] = *(unsigned short*)&hb;
    g_w2l[g][o] = *(unsigned short*)&lb;
}

__global__ void deg_fused(const int* __restrict__ ei0, const int* __restrict__ ei1) {
    int idx = blockIdx.x * 256 + threadIdx.x;
    if (idx < 2*NE) {
        int g = idx / NE, e = idx - g*NE;
        const int* ei = g ? ei1 : ei0;
        atomicAdd(&g_deg[g][ei[NE + e]], 1);
    }
}

__global__ void scan_fused() {
    __shared__ int ss[1024];
    int g = blockIdx.x;
    int t = threadIdx.x;
    const int CH = (NN + 1023) / 1024;
    int beg = t * CH, end = beg + CH;
    if (end > NN) end = NN;
    if (beg > NN) beg = NN;
    int s = 0;
    for (int i = beg; i < end; i++) s += g_deg[g][i];
    ss[t] = s;
    __syncthreads();
    for (int off = 1; off < 1024; off <<= 1) {
        int v = (t >= off) ? ss[t-off] : 0;
        __syncthreads();
        ss[t] += v;
        __syncthreads();
    }
    int run = (t == 0) ? 0 : ss[t-1];
    for (int i = beg; i < end; i++) {
        g_offs[g][i] = run; g_cursor[g][i] = run; run += g_deg[g][i];
    }
    if (t == 1023) g_offs[g][NN] = NE;
}

__global__ void dinv_kernel() {
    int idx = blockIdx.x * 256 + threadIdx.x;
    if (idx < 2*NN) {
        int g = idx / NN, i = idx - g*NN;
        g_dinv[g][i] = rsqrtf(1.f + (float)g_deg[g][i]);
    }
}

__global__ void fill_fused(const int* __restrict__ ei0, const int* __restrict__ ei1) {
    int idx = blockIdx.x * 256 + threadIdx.x;
    if (idx < 2*NE) {
        int g = idx / NE, e = idx - g*NE;
        const int* ei = g ? ei1 : ei0;
        int d = ei[NE + e];
        int p = atomicAdd(&g_cursor[g][d], 1);
        g_ssrc[g][p] = ei[e];
        g_sdst[g][p] = d;
    }
}

// ------- pointnet: 64 sorted edges x 256 ch per CTA, 256 thr, 2 CTA/SM -------
#define OFF_AH 0
#define OFF_AL 9216
#define OFF_WH 18432
#define OFF_WL 55296
#define OFF_DST 92160
#define PN_SMEM 92672
#define TILES_PER_G 6250

__global__ __launch_bounds__(256, 2)
void pointnet_mma(const float* __restrict__ b20, const float* __restrict__ b21) {
    extern __shared__ char AB[];
    uint32_t abu = smem_u32(AB);
    int tid = threadIdx.x, lane = tid & 31, wid = tid >> 5;
    int g = (blockIdx.x >= TILES_PER_G) ? 1 : 0;
    int e0 = (blockIdx.x - g*TILES_PER_G) * 64;
    const float* __restrict__ b2 = g ? b21 : b20;
    int* s_dst = (int*)(AB + OFF_DST);
    if (tid < 64) s_dst[tid] = g_sdst[g][e0 + tid];

    // gather assignment: edge = tid>>2 (0..63), k quarter = (tid&3)*16
    int ge = tid >> 2, kq = (tid & 3) * 16;
    int esrc = g_ssrc[g][e0 + ge] * 256;
    int edst = g_sdst[g][e0 + ge] * 256;
    const float* __restrict__ Aa = g_a[g];
    const float* __restrict__ Cc = g_c[g];

    // warp tiling: 2 edge-groups x 4 ch-groups; warp tile 32 edges x 64 ch
    int eg = wid >> 2, cg = wid & 3;
    int qrow = lane >> 2;
    int qc = (lane & 3) * 2;

    uint32_t aH = abu + OFF_AH + (uint32_t)(eg*32 + (lane & 15))*144 + (lane >> 4)*16;
    uint32_t aL = aH + (OFF_AL - OFF_AH);
    uint32_t bH = abu + OFF_WH +
        (uint32_t)(cg*64 + (lane >> 4)*8 + (lane & 7))*144 + ((lane >> 3) & 1)*16;
    uint32_t bL = bH + (OFF_WL - OFF_WH);

    float acc[2][8][4];
#pragma unroll
    for (int mt = 0; mt < 2; mt++)
#pragma unroll
        for (int nt = 0; nt < 8; nt++)
#pragma unroll
            for (int j = 0; j < 4; j++) acc[mt][nt][j] = 0.f;

    for (int ck = 0; ck < 4; ck++) {
        // ---- gather + bf16 split ----
        {
            int k0 = ck*64 + kq;
            float4 av[4], cv[4];
#pragma unroll
            for (int q = 0; q < 4; q++) {
                av[q] = *(const float4*)(Aa + esrc + k0 + q*4);
                cv[q] = *(const float4*)(Cc + edst + k0 + q*4);
            }
            char* ph = AB + OFF_AH + ge*0 + (tid >> 2)*144 + kq*2;
            char* pl = AB + OFF_AL + (tid >> 2)*144 + kq*2;
#pragma unroll
            for (int q = 0; q < 4; q++) {
                float h0 = fmaxf(av[q].x - cv[q].x, 0.f);
                float h1 = fmaxf(av[q].y - cv[q].y, 0.f);
                float h2 = fmaxf(av[q].z - cv[q].z, 0.f);
                float h3 = fmaxf(av[q].w - cv[q].w, 0.f);
                uint32_t hi0, hi1, lo0, lo1;
                asm("cvt.rn.bf16x2.f32 %0, %1, %2;" : "=r"(hi0) : "f"(h1), "f"(h0));
                asm("cvt.rn.bf16x2.f32 %0, %1, %2;" : "=r"(hi1) : "f"(h3), "f"(h2));
                float r0 = h0 - __uint_as_float(hi0 << 16);
                float r1 = h1 - __uint_as_float(hi0 & 0xffff0000u);
                float r2 = h2 - __uint_as_float(hi1 << 16);
                float r3 = h3 - __uint_as_float(hi1 & 0xffff0000u);
                asm("cvt.rn.bf16x2.f32 %0, %1, %2;" : "=r"(lo0) : "f"(r1), "f"(r0));
                asm("cvt.rn.bf16x2.f32 %0, %1, %2;" : "=r"(lo1) : "f"(r3), "f"(r2));
                *(uint32_t*)(ph + q*8)     = hi0;
                *(uint32_t*)(ph + q*8 + 4) = hi1;
                *(uint32_t*)(pl + q*8)     = lo0;
                *(uint32_t*)(pl + q*8 + 4) = lo1;
            }
        }
        // ---- stream W chunk [n][64] hi+lo (2048 uint4 each) ----
        {
            const uint4* gh4 = (const uint4*)(g_w2h[g] + ck*16384);
            const uint4* gl4 = (const uint4*)(g_w2l[g] + ck*16384);
#pragma unroll
            for (int i = 0; i < 8; i++) {
                int idx = tid + i*256;
                int row = idx >> 3, q = idx & 7;
                *(uint4*)(AB + OFF_WH + row*144 + q*16) = gh4[idx];
                *(uint4*)(AB + OFF_WL + row*144 + q*16) = gl4[idx];
            }
        }
        __syncthreads();

        // ---- MMA over 4 k-steps of 16; three passes ----
#pragma unroll
        for (int kk = 0; kk < 4; kk++) {
            uint32_t ko = kk*32;
            uint32_t bh[4][4], bl[4][4];
#pragma unroll
            for (int p = 0; p < 4; p++) {
                ldsm4(bh[p], bH + p*(16*144) + ko);
                ldsm4(bl[p], bL + p*(16*144) + ko);
            }
#pragma unroll
            for (int mt = 0; mt < 2; mt++) {
                uint32_t ah[4];
                ldsm4(ah, aH + mt*(16*144) + ko);
#pragma unroll
                for (int p = 0; p < 4; p++) {
                    mma_bf16(acc[mt][2*p],   ah, bh[p][0], bh[p][1]);
                    mma_bf16(acc[mt][2*p+1], ah, bh[p][2], bh[p][3]);
                }
            }
#pragma unroll
            for (int mt = 0; mt < 2; mt++) {
                uint32_t al[4];
                ldsm4(al, aL + mt*(16*144) + ko);
#pragma unroll
                for (int p = 0; p < 4; p++) {
                    mma_bf16(acc[mt][2*p],   al, bh[p][0], bh[p][1]);
                    mma_bf16(acc[mt][2*p+1], al, bh[p][2], bh[p][3]);
                }
            }
#pragma unroll
            for (int mt = 0; mt < 2; mt++) {
                uint32_t ah2[4];
                ldsm4(ah2, aH + mt*(16*144) + ko);
#pragma unroll
                for (int p = 0; p < 4; p++) {
                    mma_bf16(acc[mt][2*p],   ah2, bl[p][0], bl[p][1]);
                    mma_bf16(acc[mt][2*p+1], ah2, bl[p][2], bl[p][3]);
                }
            }
        }
        __syncthreads();
    }

    // ---- epilogue: accum -> buf[64][257] -> segmented max -> atomics ----
    float* buf = (float*)AB;
#pragma unroll
    for (int mt = 0; mt < 2; mt++) {
        int row = eg*32 + mt*16 + qrow;
#pragma unroll
        for (int nt = 0; nt < 8; nt++) {
            int col = cg*64 + nt*8 + qc;
            buf[row*257 + col]       = acc[mt][nt][0];
            buf[row*257 + col + 1]   = acc[mt][nt][1];
            buf[(row+8)*257 + col]   = acc[mt][nt][2];
            buf[(row+8)*257 + col+1] = acc[mt][nt][3];
        }
    }
    __syncthreads();
    {
        unsigned* __restrict__ seg = &g_segout[g][0];
        int gch = tid;                 // 256 channels, one per thread
        float bias = b2[gch];
        int cur = s_dst[0];
        float mx = buf[gch];
        for (int q = 1; q < 64; q++) {
            int d = s_dst[q];
            float v = buf[q*257 + gch];
            if (d != cur) {
                atomicMax(&seg[cur*256 + gch], fmap(mx + bias));
                cur = d; mx = v;
            } else mx = fmaxf(mx, v);
        }
        atomicMax(&seg[cur*256 + gch], fmap(mx + bias));
    }
}

// ------- xw = decode(segout) @ gW : [N,512]@[512,128], both graphs -------
#define XW_BLKS ((NN + 63)/64)
__global__ __launch_bounds__(256)
void xw_fused(const float* __restrict__ Wg0, const float* __restrict__ Wg1) {
    __shared__ float s_a[64*16];
    __shared__ float4 s_b[16*32];
    int g = (blockIdx.x >= XW_BLKS) ? 1 : 0;
    int row0 = (blockIdx.x - g*XW_BLKS) * 64;
    const float* __restrict__ Wg = g ? Wg1 : Wg0;
    int tid = threadIdx.x, tx = tid & 31, ty = tid >> 5;
    float acc[8][4];
#pragma unroll
    for (int i = 0; i < 8; i++)
#pragma unroll
        for (int j = 0; j < 4; j++) acc[i][j] = 0.f;
    int lr = tid >> 2, lk = (tid & 3) * 4;
    int ar = row0 + lr; if (ar > NN-1) ar = NN-1;
    const float4* B4 = (const float4*)Wg;
    for (int k0 = 0; k0 < 512; k0 += 16) {
        int kk0 = k0 + lk;
        const unsigned* sp = (kk0 < 256) ? &g_segout[0][ar*256 + kk0]
                                         : &g_segout[1][ar*256 + kk0 - 256];
        uint4 u = *(const uint4*)sp;
        float4 av;
        av.x = (u.x > 0x80000000u) ? __uint_as_float(u.x ^ 0x80000000u) : 0.f;
        av.y = (u.y > 0x80000000u) ? __uint_as_float(u.y ^ 0x80000000u) : 0.f;
        av.z = (u.z > 0x80000000u) ? __uint_as_float(u.z ^ 0x80000000u) : 0.f;
        av.w = (u.w > 0x80000000u) ? __uint_as_float(u.w ^ 0x80000000u) : 0.f;
        float4 bv[2];
#pragma unroll
        for (int q = 0; q < 2; q++) {
            int idx = tid + q*256;
            bv[q] = B4[(k0 + (idx >> 5))*32 + (idx & 31)];
        }
        __syncthreads();
        *(float4*)(s_a + lr*16 + lk) = av;
#pragma unroll
        for (int q = 0; q < 2; q++) s_b[tid + q*256] = bv[q];
        __syncthreads();
#pragma unroll
        for (int kk = 0; kk < 16; kk++) {
            float4 b = s_b[kk*32 + tx];
#pragma unroll
            for (int i = 0; i < 8; i++) {
                float a = s_a[(ty*8 + i)*16 + kk];
                acc[i][0] += a*b.x; acc[i][1] += a*b.y;
                acc[i][2] += a*b.z; acc[i][3] += a*b.w;
            }
        }
    }
#pragma unroll
    for (int i = 0; i < 8; i++) {
        int r = row0 + ty*8 + i;
        if (r < NN)
            *(float4*)(g_xw[g] + r*128 + tx*4) =
                make_float4(acc[i][0], acc[i][1], acc[i][2], acc[i][3]);
    }
}

__global__ void agg_fused(const float* __restrict__ gb0, const float* __restrict__ gb1) {
    int g = (blockIdx.x >= NN) ? 1 : 0;
    int i = blockIdx.x - g*NN;
    int ch = threadIdx.x;
    const float* __restrict__ xw = g_xw[g];
    const float* __restrict__ bias = g ? gb1 : gb0;
    float di = g_dinv[g][i];
    int beg = g_offs[g][i], end = g_offs[g][i+1];
    float acc = 0.f;
    for (int e = beg; e < end; e++) {
        int s = g_ssrc[g][e];
        acc += xw[s*128 + ch] * g_dinv[g][s];
    }
    float v = di*acc + xw[i*128 + ch]*di*di + bias[ch];
    g_h2[i*256 + g*128 + ch] = fmaxf(v, 0.f);
}

__global__ __launch_bounds__(256)
void c3cls_kernel(const float* __restrict__ Wc, const float* __restrict__ bc,
                  const float* __restrict__ clsW) {
    __shared__ float s_a[64*16];
    __shared__ float4 s_b[16*32];
    __shared__ float red[256];
    int tid = threadIdx.x, tx = tid & 31, ty = tid >> 5;
    int row0 = blockIdx.x * 64;
    float acc[8][4];
#pragma unroll
    for (int i = 0; i < 8; i++)
#pragma unroll
        for (int j = 0; j < 4; j++) acc[i][j] = 0.f;
    int lr = tid >> 2, lk = (tid & 3) * 4;
    int ar = row0 + lr; if (ar > NN-1) ar = NN-1;
    const float4* B4 = (const float4*)Wc;
    for (int k0 = 0; k0 < 256; k0 += 16) {
        float4 av = *(const float4*)(g_h2 + ar*256 + k0 + lk);
        float4 bv[2];
#pragma unroll
        for (int q = 0; q < 2; q++) {
            int idx = tid + q*256;
            bv[q] = B4[(k0 + (idx >> 5))*32 + (idx & 31)];
        }
        __syncthreads();
        *(float4*)(s_a + lr*16 + lk) = av;
#pragma unroll
        for (int q = 0; q < 2; q++) s_b[tid + q*256] = bv[q];
        __syncthreads();
#pragma unroll
        for (int kk = 0; kk < 16; kk++) {
            float4 b = s_b[kk*32 + tx];
#pragma unroll
            for (int i = 0; i < 8; i++) {
                float a = s_a[(ty*8 + i)*16 + kk];
                acc[i][0] += a*b.x; acc[i][1] += a*b.y;
                acc[i][2] += a*b.z; acc[i][3] += a*b.w;
            }
        }
    }
    float sum0 = 0.f, sum1 = 0.f, sum2 = 0.f;
#pragma unroll
    for (int i = 0; i < 8; i++) {
        int r = row0 + ty*8 + i;
        if (r < NN) {
#pragma unroll
            for (int jj = 0; jj < 4; jj++) {
                float v = fmaxf(acc[i][jj] + bc[tx*4 + jj], 0.f);
                const float* w = clsW + (r*128 + tx*4 + jj)*3;
                sum0 += v*w[0]; sum1 += v*w[1]; sum2 += v*w[2];
            }
        }
    }
    float sums[3] = {sum0, sum1, sum2};
#pragma unroll
    for (int r3 = 0; r3 < 3; r3++) {
        red[tid] = sums[r3];
        __syncthreads();
        for (int s = 128; s > 0; s >>= 1) {
            if (tid < s) red[tid] += red[tid + s];
            __syncthreads();
        }
        if (tid == 0) g_partial[blockIdx.x*3 + r3] = red[0];
        __syncthreads();
    }
}

__global__ void final_kernel(const float* __restrict__ clsb, float* __restrict__ out, int nblk) {
    int r = threadIdx.x;
    if (r < 3) {
        double s = (double)clsb[r];
        for (int i = 0; i < nblk; i++) s += (double)g_partial[i*3 + r];
        out[r] = (float)s;
    }
}

extern "C" void kernel_launch(void* const* d_in, const int* in_sizes, int n_in,
                              void* d_out, int out_size) {
    const float *pos[2]={0,0}, *W1[2]={0,0}, *b1[2]={0,0}, *W2[2]={0,0}, *b2[2]={0,0};
    const float *gW[2]={0,0}, *gb[2]={0,0}, *cW=0, *cb=0, *clsW=0, *clsb=0;
    const int *ei[2]={0,0};
    int npos=0, nei=0, nw1=0, n256=0, n64k=0, n128=0;
    for (int i = 0; i < n_in; i++) {
        int sz = in_sizes[i];
        const float* f = (const float*)d_in[i];
        if (sz == 3*NN)            { if (npos<2) pos[npos++] = f; }
        else if (sz == 2*NE)       { if (nei<2)  ei[nei++] = (const int*)d_in[i]; }
        else if (sz == 6*H)        { if (nw1<2)  W1[nw1++] = f; }
        else if (sz == H)          { int j=n256++; if(j==0)b1[0]=f; else if(j==1)b2[0]=f;
                                     else if(j==2)b1[1]=f; else if(j==3)b2[1]=f; }
        else if (sz == H*H)        { int j=n64k++; if(j<2) W2[j]=f; else if(j<4) gW[j-2]=f; }
        else if (sz == H/2)        { int j=n128++; if(j<2) gb[j]=f; else cb=f; }
        else if (sz == H*(H/2))    { cW = f; }
        else if (sz == NN*(H/2)*3) { clsW = f; }
        else if (sz == 3)          { clsb = f; }
    }

    static bool attr_done = false;
    if (!attr_done) {
        cudaFuncSetAttribute(pointnet_mma, cudaFuncAttributeMaxDynamicSharedMemorySize, PN_SMEM);
        attr_done = true;
    }

    init_kernel<<<(2*NN*H + 255)/256, 256>>>();
    uv_fused<<<2*NN, 256>>>(pos[0], pos[1], W1[0], W1[1], b1[0], b1[1]);
    w2prep_fused<<<512, 256>>>(W2[0], W2[1]);
    deg_fused<<<(2*NE + 255)/256, 256>>>(ei[0], ei[1]);
    scan_fused<<<2, 1024>>>();
    fill_fused<<<(2*NE + 255)/256, 256>>>(ei[0], ei[1]);
    dinv_kernel<<<(2*NN + 255)/256, 256>>>();
    pointnet_mma<<<2*TILES_PER_G, 256, PN_SMEM>>>(b2[0], b2[1]);
    xw_fused<<<2*XW_BLKS, 256>>>(gW[0], gW[1]);
    agg_fused<<<2*NN, 128>>>(gb[0], gb[1]);
    int nblk = XW_BLKS;
    c3cls_kernel<<<nblk, 256>>>(cW, cb, clsW);
    final_kernel<<<1, 32>>>(clsb, (float*)d_out, nblk);
}

// round 12
// speedup vs baseline: 2.5556x; 1.0444x over previous
#include <cuda_runtime.h>
#include <cuda_bf16.h>
#include <cstdint>

#define NN 20000
#define NE 400000
#define H  256

// ------- static scratch (allocations forbidden) -------
__device__ float    g_a[2][NN*H];
__device__ float    g_c[2][NN*H];
__device__ unsigned g_segout[2][NN*H];   // mapped-uint running max, 0 = empty
__device__ float    g_xw[2][NN*128];
__device__ float    g_h2[NN*256];
__device__ int      g_deg[2][NN];
__device__ int      g_offs[2][NN+1];
__device__ int      g_cursor[2][NN];
__device__ int      g_ssrc[2][NE];
__device__ int      g_sdst[2][NE];
__device__ float    g_dinv[2][NN];
__device__ float    g_partial[1024*3];
__device__ unsigned short g_w2h[2][H*H];  // bf16 hi of W2^T, [chunk][n][64k]
__device__ unsigned short g_w2l[2][H*H];  // bf16 lo
__device__ unsigned short g_gwh[2][512*128]; // bf16 hi of gW^T, [chunk8][n128][64k]
__device__ unsigned short g_gwl[2][512*128];

__device__ __forceinline__ unsigned fmap(float f) {
    unsigned b = __float_as_uint(f);
    return b ^ ((unsigned)((int)b >> 31) | 0x80000000u);
}
__device__ __forceinline__ uint32_t smem_u32(const void* p) {
    uint32_t a;
    asm("{ .reg .u64 t; cvta.to.shared.u64 t, %1; cvt.u32.u64 %0, t; }" : "=r"(a) : "l"(p));
    return a;
}
__device__ __forceinline__ void mma_bf16(float* c, const uint32_t* a,
                                         uint32_t b0, uint32_t b1) {
    asm("mma.sync.aligned.m16n8k16.row.col.f32.bf16.bf16.f32 "
        "{%0,%1,%2,%3}, {%4,%5,%6,%7}, {%8,%9}, {%0,%1,%2,%3};"
        : "+f"(c[0]), "+f"(c[1]), "+f"(c[2]), "+f"(c[3])
        : "r"(a[0]), "r"(a[1]), "r"(a[2]), "r"(a[3]), "r"(b0), "r"(b1));
}
__device__ __forceinline__ void ldsm4(uint32_t* r, uint32_t addr) {
    asm volatile("ldmatrix.sync.aligned.m8n8.x4.shared.b16 {%0,%1,%2,%3}, [%4];"
        : "=r"(r[0]), "=r"(r[1]), "=r"(r[2]), "=r"(r[3]) : "r"(addr));
}
__device__ __forceinline__ void bf16split(float h, float h1, uint32_t& hi, uint32_t& lo) {
    asm("cvt.rn.bf16x2.f32 %0, %1, %2;" : "=r"(hi) : "f"(h1), "f"(h));
    float r0 = h - __uint_as_float(hi << 16);
    float r1 = h1 - __uint_as_float(hi & 0xffff0000u);
    asm("cvt.rn.bf16x2.f32 %0, %1, %2;" : "=r"(lo) : "f"(r1), "f"(r0));
}

// ------- fused prep kernels -------
__global__ void init_kernel() {
    int idx = blockIdx.x * 256 + threadIdx.x;
    if (idx < 2*NN*H) (&g_segout[0][0])[idx] = 0u;
    if (idx < 2*NN)   (&g_deg[0][0])[idx] = 0;
}

__global__ void uv_fused(const float* __restrict__ pos0, const float* __restrict__ pos1,
                         const float* __restrict__ W10, const float* __restrict__ W11,
                         const float* __restrict__ b10, const float* __restrict__ b11) {
    int g = blockIdx.x / NN, i = blockIdx.x - g*NN, ch = threadIdx.x;
    const float* pos = g ? pos1 : pos0;
    const float* W1  = g ? W11 : W10;
    const float* bb  = g ? b11 : b10;
    float p0 = pos[i*3+0], p1 = pos[i*3+1], p2 = pos[i*3+2];
    float c = p0*W1[3*H+ch] + p1*W1[4*H+ch] + p2*W1[5*H+ch];
    float a = p0*W1[0*H+ch] + p1*W1[1*H+ch] + p2*W1[2*H+ch] + c + bb[ch];
    g_a[g][i*H+ch] = a;
    g_c[g][i*H+ch] = c;
}

__global__ void w2prep_fused(const float* __restrict__ W20, const float* __restrict__ W21) {
    int g = blockIdx.x >> 8;
    int idx = (blockIdx.x & 255) * 256 + threadIdx.x;  // k*256+n
    int k = idx >> 8, n = idx & 255;
    float w = (g ? W21 : W20)[idx];
    __nv_bfloat16 hb = __float2bfloat16(w);
    float hf = __bfloat162float(hb);
    __nv_bfloat16 lb = __float2bfloat16(w - hf);
    int o = (k >> 6)*16384 + n*64 + (k & 63);
    g_w2h[g][o] = *(unsigned short*)&hb;
    g_w2l[g][o] = *(unsigned short*)&lb;
}

// gW [512,128] -> bf16 split, transposed [chunk8][n128][64k]
__global__ void gwprep_fused(const float* __restrict__ Wg0, const float* __restrict__ Wg1) {
    int g = blockIdx.x >> 8;
    int idx = (blockIdx.x & 255) * 256 + threadIdx.x;  // k*128+n over 65536
    int k = idx >> 7, n = idx & 127;
    float w = (g ? Wg1 : Wg0)[idx];
    __nv_bfloat16 hb = __float2bfloat16(w);
    float hf = __bfloat162float(hb);
    __nv_bfloat16 lb = __float2bfloat16(w - hf);
    int o = (k >> 6)*8192 + n*64 + (k & 63);
    g_gwh[g][o] = *(unsigned short*)&hb;
    g_gwl[g][o] = *(unsigned short*)&lb;
}

__global__ void deg_fused(const int* __restrict__ ei0, const int* __restrict__ ei1) {
    int idx = blockIdx.x * 256 + threadIdx.x;
    if (idx < 2*NE) {
        int g = idx / NE, e = idx - g*NE;
        const int* ei = g ? ei1 : ei0;
        atomicAdd(&g_deg[g][ei[NE + e]], 1);
    }
}

__global__ void scan_fused() {
    __shared__ int ss[1024];
    int g = blockIdx.x;
    int t = threadIdx.x;
    const int CH = (NN + 1023) / 1024;
    int beg = t * CH, end = beg + CH;
    if (end > NN) end = NN;
    if (beg > NN) beg = NN;
    int s = 0;
    for (int i = beg; i < end; i++) s += g_deg[g][i];
    ss[t] = s;
    __syncthreads();
    for (int off = 1; off < 1024; off <<= 1) {
        int v = (t >= off) ? ss[t-off] : 0;
        __syncthreads();
        ss[t] += v;
        __syncthreads();
    }
    int run = (t == 0) ? 0 : ss[t-1];
    for (int i = beg; i < end; i++) {
        g_offs[g][i] = run; g_cursor[g][i] = run; run += g_deg[g][i];
    }
    if (t == 1023) g_offs[g][NN] = NE;
}

__global__ void dinv_kernel() {
    int idx = blockIdx.x * 256 + threadIdx.x;
    if (idx < 2*NN) {
        int g = idx / NN, i = idx - g*NN;
        g_dinv[g][i] = rsqrtf(1.f + (float)g_deg[g][i]);
    }
}

__global__ void fill_fused(const int* __restrict__ ei0, const int* __restrict__ ei1) {
    int idx = blockIdx.x * 256 + threadIdx.x;
    if (idx < 2*NE) {
        int g = idx / NE, e = idx - g*NE;
        const int* ei = g ? ei1 : ei0;
        int d = ei[NE + e];
        int p = atomicAdd(&g_cursor[g][d], 1);
        g_ssrc[g][p] = ei[e];
        g_sdst[g][p] = d;
    }
}

// ------- pointnet: 64 sorted edges x 256 ch per CTA, 256 thr, 2 CTA/SM -------
#define OFF_AH 0
#define OFF_AL 9216
#define OFF_WH 18432
#define OFF_WL 55296
#define OFF_DST 92160
#define PN_SMEM 92672
#define TILES_PER_G 6250

__global__ __launch_bounds__(256, 2)
void pointnet_mma(const float* __restrict__ b20, const float* __restrict__ b21) {
    extern __shared__ char AB[];
    uint32_t abu = smem_u32(AB);
    int tid = threadIdx.x, lane = tid & 31, wid = tid >> 5;
    int g = (blockIdx.x >= TILES_PER_G) ? 1 : 0;
    int e0 = (blockIdx.x - g*TILES_PER_G) * 64;
    const float* __restrict__ b2 = g ? b21 : b20;
    int* s_dst = (int*)(AB + OFF_DST);
    if (tid < 64) s_dst[tid] = g_sdst[g][e0 + tid];

    int ge = tid >> 2, kq = (tid & 3) * 16;
    int esrc = g_ssrc[g][e0 + ge] * 256;
    int edst = g_sdst[g][e0 + ge] * 256;
    const float* __restrict__ Aa = g_a[g];
    const float* __restrict__ Cc = g_c[g];

    int eg = wid >> 2, cg = wid & 3;
    int qrow = lane >> 2;
    int qc = (lane & 3) * 2;

    uint32_t aH = abu + OFF_AH + (uint32_t)(eg*32 + (lane & 15))*144 + (lane >> 4)*16;
    uint32_t aL = aH + (OFF_AL - OFF_AH);
    uint32_t bH = abu + OFF_WH +
        (uint32_t)(cg*64 + (lane >> 4)*8 + (lane & 7))*144 + ((lane >> 3) & 1)*16;
    uint32_t bL = bH + (OFF_WL - OFF_WH);

    float acc[2][8][4];
#pragma unroll
    for (int mt = 0; mt < 2; mt++)
#pragma unroll
        for (int nt = 0; nt < 8; nt++)
#pragma unroll
            for (int j = 0; j < 4; j++) acc[mt][nt][j] = 0.f;

    for (int ck = 0; ck < 4; ck++) {
        {
            int k0 = ck*64 + kq;
            float4 av[4], cv[4];
#pragma unroll
            for (int q = 0; q < 4; q++) {
                av[q] = *(const float4*)(Aa + esrc + k0 + q*4);
                cv[q] = *(const float4*)(Cc + edst + k0 + q*4);
            }
            char* ph = AB + OFF_AH + (tid >> 2)*144 + kq*2;
            char* pl = AB + OFF_AL + (tid >> 2)*144 + kq*2;
#pragma unroll
            for (int q = 0; q < 4; q++) {
                float h0 = fmaxf(av[q].x - cv[q].x, 0.f);
                float h1 = fmaxf(av[q].y - cv[q].y, 0.f);
                float h2 = fmaxf(av[q].z - cv[q].z, 0.f);
                float h3 = fmaxf(av[q].w - cv[q].w, 0.f);
                uint32_t hi0, hi1, lo0, lo1;
                bf16split(h0, h1, hi0, lo0);
                bf16split(h2, h3, hi1, lo1);
                *(uint32_t*)(ph + q*8)     = hi0;
                *(uint32_t*)(ph + q*8 + 4) = hi1;
                *(uint32_t*)(pl + q*8)     = lo0;
                *(uint32_t*)(pl + q*8 + 4) = lo1;
            }
        }
        {
            const uint4* gh4 = (const uint4*)(g_w2h[g] + ck*16384);
            const uint4* gl4 = (const uint4*)(g_w2l[g] + ck*16384);
#pragma unroll
            for (int i = 0; i < 8; i++) {
                int idx = tid + i*256;
                int row = idx >> 3, q = idx & 7;
                *(uint4*)(AB + OFF_WH + row*144 + q*16) = gh4[idx];
                *(uint4*)(AB + OFF_WL + row*144 + q*16) = gl4[idx];
            }
        }
        __syncthreads();

#pragma unroll
        for (int kk = 0; kk < 4; kk++) {
            uint32_t ko = kk*32;
            uint32_t bh[4][4], bl[4][4];
#pragma unroll
            for (int p = 0; p < 4; p++) {
                ldsm4(bh[p], bH + p*(16*144) + ko);
                ldsm4(bl[p], bL + p*(16*144) + ko);
            }
#pragma unroll
            for (int mt = 0; mt < 2; mt++) {
                uint32_t ah[4];
                ldsm4(ah, aH + mt*(16*144) + ko);
#pragma unroll
                for (int p = 0; p < 4; p++) {
                    mma_bf16(acc[mt][2*p],   ah, bh[p][0], bh[p][1]);
                    mma_bf16(acc[mt][2*p+1], ah, bh[p][2], bh[p][3]);
                }
            }
#pragma unroll
            for (int mt = 0; mt < 2; mt++) {
                uint32_t al[4];
                ldsm4(al, aL + mt*(16*144) + ko);
#pragma unroll
                for (int p = 0; p < 4; p++) {
                    mma_bf16(acc[mt][2*p],   al, bh[p][0], bh[p][1]);
                    mma_bf16(acc[mt][2*p+1], al, bh[p][2], bh[p][3]);
                }
            }
#pragma unroll
            for (int mt = 0; mt < 2; mt++) {
                uint32_t ah2[4];
                ldsm4(ah2, aH + mt*(16*144) + ko);
#pragma unroll
                for (int p = 0; p < 4; p++) {
                    mma_bf16(acc[mt][2*p],   ah2, bl[p][0], bl[p][1]);
                    mma_bf16(acc[mt][2*p+1], ah2, bl[p][2], bl[p][3]);
                }
            }
        }
        __syncthreads();
    }

    float* buf = (float*)AB;
#pragma unroll
    for (int mt = 0; mt < 2; mt++) {
        int row = eg*32 + mt*16 + qrow;
#pragma unroll
        for (int nt = 0; nt < 8; nt++) {
            int col = cg*64 + nt*8 + qc;
            buf[row*257 + col]       = acc[mt][nt][0];
            buf[row*257 + col + 1]   = acc[mt][nt][1];
            buf[(row+8)*257 + col]   = acc[mt][nt][2];
            buf[(row+8)*257 + col+1] = acc[mt][nt][3];
        }
    }
    __syncthreads();
    {
        unsigned* __restrict__ seg = &g_segout[g][0];
        int gch = tid;
        float bias = b2[gch];
        int cur = s_dst[0];
        float mx = buf[gch];
        for (int q = 1; q < 64; q++) {
            int d = s_dst[q];
            float v = buf[q*257 + gch];
            if (d != cur) {
                atomicMax(&seg[cur*256 + gch], fmap(mx + bias));
                cur = d; mx = v;
            } else mx = fmaxf(mx, v);
        }
        atomicMax(&seg[cur*256 + gch], fmap(mx + bias));
    }
}

// ------- xw via HMMA: [NN,512]@[512,128] per graph, 3-term bf16 -------
#define XOFF_AH 0
#define XOFF_AL 18432
#define XOFF_WH 36864
#define XOFF_WL 55296
#define XW_SMEM 73728
#define XW_TILES 157

__global__ __launch_bounds__(256, 2)
void xw_mma() {
    extern __shared__ char AB[];
    uint32_t abu = smem_u32(AB);
    int tid = threadIdx.x, lane = tid & 31, wid = tid >> 5;
    int g = (blockIdx.x >= XW_TILES) ? 1 : 0;
    int row0 = (blockIdx.x - g*XW_TILES) * 128;

    int grow = tid >> 1, kh = (tid & 1) * 32;  // gather: 2 threads/row, 32 k each
    int ar = row0 + grow; if (ar > NN-1) ar = NN-1;

    int eg = wid >> 1, cg = wid & 1;
    int qrow = lane >> 2;
    int qc = (lane & 3) * 2;

    uint32_t aH = abu + XOFF_AH + (uint32_t)(eg*32 + (lane & 15))*144 + (lane >> 4)*16;
    uint32_t aL = aH + (XOFF_AL - XOFF_AH);
    uint32_t bH = abu + XOFF_WH +
        (uint32_t)(cg*64 + (lane >> 4)*8 + (lane & 7))*144 + ((lane >> 3) & 1)*16;
    uint32_t bL = bH + (XOFF_WL - XOFF_WH);

    float acc[2][8][4];
#pragma unroll
    for (int mt = 0; mt < 2; mt++)
#pragma unroll
        for (int nt = 0; nt < 8; nt++)
#pragma unroll
            for (int j = 0; j < 4; j++) acc[mt][nt][j] = 0.f;

    for (int ck = 0; ck < 8; ck++) {
        // decode segout rows -> bf16 split
        {
            int kbase = ck*64 + kh;  // global k in [0,512)
            const unsigned* sp = (kbase < 256) ? &g_segout[0][ar*256 + kbase]
                                               : &g_segout[1][ar*256 + kbase - 256];
            char* ph = AB + XOFF_AH + grow*144 + kh*2;
            char* pl = AB + XOFF_AL + grow*144 + kh*2;
#pragma unroll
            for (int q = 0; q < 8; q++) {
                uint4 u = *(const uint4*)(sp + q*4);
                float h0 = (u.x > 0x80000000u) ? __uint_as_float(u.x ^ 0x80000000u) : 0.f;
                float h1 = (u.y > 0x80000000u) ? __uint_as_float(u.y ^ 0x80000000u) : 0.f;
                float h2 = (u.z > 0x80000000u) ? __uint_as_float(u.z ^ 0x80000000u) : 0.f;
                float h3 = (u.w > 0x80000000u) ? __uint_as_float(u.w ^ 0x80000000u) : 0.f;
                uint32_t hi0, hi1, lo0, lo1;
                bf16split(h0, h1, hi0, lo0);
                bf16split(h2, h3, hi1, lo1);
                *(uint32_t*)(ph + q*8)     = hi0;
                *(uint32_t*)(ph + q*8 + 4) = hi1;
                *(uint32_t*)(pl + q*8)     = lo0;
                *(uint32_t*)(pl + q*8 + 4) = lo1;
            }
        }
        // stream gW chunk [n128][64k] hi+lo (1024 uint4 each)
        {
            const uint4* gh4 = (const uint4*)(g_gwh[g] + ck*8192);
            const uint4* gl4 = (const uint4*)(g_gwl[g] + ck*8192);
#pragma unroll
            for (int i = 0; i < 4; i++) {
                int idx = tid + i*256;
                int row = idx >> 3, q = idx & 7;
                *(uint4*)(AB + XOFF_WH + row*144 + q*16) = gh4[idx];
                *(uint4*)(AB + XOFF_WL + row*144 + q*16) = gl4[idx];
            }
        }
        __syncthreads();

#pragma unroll
        for (int kk = 0; kk < 4; kk++) {
            uint32_t ko = kk*32;
            uint32_t bh[4][4], bl[4][4];
#pragma unroll
            for (int p = 0; p < 4; p++) {
                ldsm4(bh[p], bH + p*(16*144) + ko);
                ldsm4(bl[p], bL + p*(16*144) + ko);
            }
#pragma unroll
            for (int mt = 0; mt < 2; mt++) {
                uint32_t ah[4];
                ldsm4(ah, aH + mt*(16*144) + ko);
#pragma unroll
                for (int p = 0; p < 4; p++) {
                    mma_bf16(acc[mt][2*p],   ah, bh[p][0], bh[p][1]);
                    mma_bf16(acc[mt][2*p+1], ah, bh[p][2], bh[p][3]);
                }
            }
#pragma unroll
            for (int mt = 0; mt < 2; mt++) {
                uint32_t al[4];
                ldsm4(al, aL + mt*(16*144) + ko);
#pragma unroll
                for (int p = 0; p < 4; p++) {
                    mma_bf16(acc[mt][2*p],   al, bh[p][0], bh[p][1]);
                    mma_bf16(acc[mt][2*p+1], al, bh[p][2], bh[p][3]);
                }
            }
#pragma unroll
            for (int mt = 0; mt < 2; mt++) {
                uint32_t ah2[4];
                ldsm4(ah2, aH + mt*(16*144) + ko);
#pragma unroll
                for (int p = 0; p < 4; p++) {
                    mma_bf16(acc[mt][2*p],   ah2, bl[p][0], bl[p][1]);
                    mma_bf16(acc[mt][2*p+1], ah2, bl[p][2], bl[p][3]);
                }
            }
        }
        __syncthreads();
    }

    // epilogue: fragments -> g_xw directly
    float* __restrict__ xw = g_xw[g];
#pragma unroll
    for (int mt = 0; mt < 2; mt++) {
        int r0 = row0 + eg*32 + mt*16 + qrow;
#pragma unroll
        for (int nt = 0; nt < 8; nt++) {
            int col = cg*64 + nt*8 + qc;
            if (r0 < NN)
                *(float2*)(xw + r0*128 + col) = make_float2(acc[mt][nt][0], acc[mt][nt][1]);
            if (r0 + 8 < NN)
                *(float2*)(xw + (r0+8)*128 + col) = make_float2(acc[mt][nt][2], acc[mt][nt][3]);
        }
    }
}

// ------- agg: one block per node, both graphs, float2 channels -------
__global__ void agg_paired(const float* __restrict__ gb0, const float* __restrict__ gb1) {
    int i = blockIdx.x;
    int t = threadIdx.x;
    int g = t >> 6;                 // warps 0-1: g=0, warps 2-3: g=1
    int ch = (t & 63) * 2;
    const float* __restrict__ xw = g_xw[g];
    const float* __restrict__ bias = g ? gb1 : gb0;
    float di = g_dinv[g][i];
    int beg = g_offs[g][i], end = g_offs[g][i+1];
    float ax = 0.f, ay = 0.f;
    for (int e = beg; e < end; e++) {
        int s = g_ssrc[g][e];
        float2 v = *(const float2*)(xw + s*128 + ch);
        float dv = g_dinv[g][s];
        ax += v.x * dv; ay += v.y * dv;
    }
    float2 self = *(const float2*)(xw + i*128 + ch);
    float d2 = di*di;
    float vx = di*ax + self.x*d2 + bias[ch];
    float vy = di*ay + self.y*d2 + bias[ch+1];
    *(float2*)(&g_h2[i*256 + g*128 + ch]) = make_float2(fmaxf(vx, 0.f), fmaxf(vy, 0.f));
}

__global__ __launch_bounds__(256)
void c3cls_kernel(const float* __restrict__ Wc, const float* __restrict__ bc,
                  const float* __restrict__ clsW) {
    __shared__ float s_a[64*16];
    __shared__ float4 s_b[16*32];
    __shared__ float red[256];
    int tid = threadIdx.x, tx = tid & 31, ty = tid >> 5;
    int row0 = blockIdx.x * 64;
    float acc[8][4];
#pragma unroll
    for (int i = 0; i < 8; i++)
#pragma unroll
        for (int j = 0; j < 4; j++) acc[i][j] = 0.f;
    int lr = tid >> 2, lk = (tid & 3) * 4;
    int ar = row0 + lr; if (ar > NN-1) ar = NN-1;
    const float4* B4 = (const float4*)Wc;
    for (int k0 = 0; k0 < 256; k0 += 16) {
        float4 av = *(const float4*)(g_h2 + ar*256 + k0 + lk);
        float4 bv[2];
#pragma unroll
        for (int q = 0; q < 2; q++) {
            int idx = tid + q*256;
            bv[q] = B4[(k0 + (idx >> 5))*32 + (idx & 31)];
        }
        __syncthreads();
        *(float4*)(s_a + lr*16 + lk) = av;
#pragma unroll
        for (int q = 0; q < 2; q++) s_b[tid + q*256] = bv[q];
        __syncthreads();
#pragma unroll
        for (int kk = 0; kk < 16; kk++) {
            float4 b = s_b[kk*32 + tx];
#pragma unroll
            for (int i = 0; i < 8; i++) {
                float a = s_a[(ty*8 + i)*16 + kk];
                acc[i][0] += a*b.x; acc[i][1] += a*b.y;
                acc[i][2] += a*b.z; acc[i][3] += a*b.w;
            }
        }
    }
    float sum0 = 0.f, sum1 = 0.f, sum2 = 0.f;
#pragma unroll
    for (int i = 0; i < 8; i++) {
        int r = row0 + ty*8 + i;
        if (r < NN) {
#pragma unroll
            for (int jj = 0; jj < 4; jj++) {
                float v = fmaxf(acc[i][jj] + bc[tx*4 + jj], 0.f);
                const float* w = clsW + (r*128 + tx*4 + jj)*3;
                sum0 += v*w[0]; sum1 += v*w[1]; sum2 += v*w[2];
            }
        }
    }
    float sums[3] = {sum0, sum1, sum2};
#pragma unroll
    for (int r3 = 0; r3 < 3; r3++) {
        red[tid] = sums[r3];
        __syncthreads();
        for (int s = 128; s > 0; s >>= 1) {
            if (tid < s) red[tid] += red[tid + s];
            __syncthreads();
        }
        if (tid == 0) g_partial[blockIdx.x*3 + r3] = red[0];
        __syncthreads();
    }
}

__global__ void final_kernel(const float* __restrict__ clsb, float* __restrict__ out, int nblk) {
    int r = threadIdx.x;
    if (r < 3) {
        double s = (double)clsb[r];
        for (int i = 0; i < nblk; i++) s += (double)g_partial[i*3 + r];
        out[r] = (float)s;
    }
}

extern "C" void kernel_launch(void* const* d_in, const int* in_sizes, int n_in,
                              void* d_out, int out_size) {
    const float *pos[2]={0,0}, *W1[2]={0,0}, *b1[2]={0,0}, *W2[2]={0,0}, *b2[2]={0,0};
    const float *gW[2]={0,0}, *gb[2]={0,0}, *cW=0, *cb=0, *clsW=0, *clsb=0;
    const int *ei[2]={0,0};
    int npos=0, nei=0, nw1=0, n256=0, n64k=0, n128=0;
    for (int i = 0; i < n_in; i++) {
        int sz = in_sizes[i];
        const float* f = (const float*)d_in[i];
        if (sz == 3*NN)            { if (npos<2) pos[npos++] = f; }
        else if (sz == 2*NE)       { if (nei<2)  ei[nei++] = (const int*)d_in[i]; }
        else if (sz == 6*H)        { if (nw1<2)  W1[nw1++] = f; }
        else if (sz == H)          { int j=n256++; if(j==0)b1[0]=f; else if(j==1)b2[0]=f;
                                     else if(j==2)b1[1]=f; else if(j==3)b2[1]=f; }
        else if (sz == H*H)        { int j=n64k++; if(j<2) W2[j]=f; else if(j<4) gW[j-2]=f; }
        else if (sz == H/2)        { int j=n128++; if(j<2) gb[j]=f; else cb=f; }
        else if (sz == H*(H/2))    { cW = f; }
        else if (sz == NN*(H/2)*3) { clsW = f; }
        else if (sz == 3)          { clsb = f; }
    }

    static bool attr_done = false;
    if (!attr_done) {
        cudaFuncSetAttribute(pointnet_mma, cudaFuncAttributeMaxDynamicSharedMemorySize, PN_SMEM);
        cudaFuncSetAttribute(xw_mma, cudaFuncAttributeMaxDynamicSharedMemorySize, XW_SMEM);
        attr_done = true;
    }

    init_kernel<<<(2*NN*H + 255)/256, 256>>>();
    uv_fused<<<2*NN, 256>>>(pos[0], pos[1], W1[0], W1[1], b1[0], b1[1]);
    w2prep_fused<<<512, 256>>>(W2[0], W2[1]);
    gwprep_fused<<<512, 256>>>(gW[0], gW[1]);
    deg_fused<<<(2*NE + 255)/256, 256>>>(ei[0], ei[1]);
    scan_fused<<<2, 1024>>>();
    fill_fused<<<(2*NE + 255)/256, 256>>>(ei[0], ei[1]);
    dinv_kernel<<<(2*NN + 255)/256, 256>>>();
    pointnet_mma<<<2*TILES_PER_G, 256, PN_SMEM>>>(b2[0], b2[1]);
    xw_mma<<<2*XW_TILES, 256, XW_SMEM>>>();
    agg_paired<<<NN, 128>>>(gb[0], gb[1]);
    int nblk = (NN + 63)/64;
    c3cls_kernel<<<nblk, 256>>>(cW, cb, clsW);
    final_kernel<<<1, 32>>>(clsb, (float*)d_out, nblk);
}

// round 14
// speedup vs baseline: 2.7994x; 1.0954x over previous
#include <cuda_runtime.h>
#include <cuda_bf16.h>
#include <cuda_fp16.h>
#include <cstdint>

#define NN 20000
#define NE 400000
#define H  256

// ------- static scratch (allocations forbidden) -------
__device__ float    g_a[2][NN*H];
__device__ float    g_c[2][NN*H];
__device__ unsigned g_segout[2][NN*H];   // mapped-uint running max, 0 = empty
__device__ float    g_xw[2][NN*128];
__device__ float    g_h2[NN*256];
__device__ int      g_deg[2][NN];
__device__ int      g_offs[2][NN+1];
__device__ int      g_cursor[2][NN];
__device__ int      g_ssrc[2][NE];
__device__ int      g_sdst[2][NE];
__device__ float    g_dinv[2][NN];
__device__ float    g_partial[1024*3];
__device__ unsigned short g_w2h[2][H*H];  // f16 hi of W2^T, [chunk][n][64k]
__device__ unsigned short g_w2l[2][H*H];  // f16 lo (exact residual)
__device__ unsigned short g_gwh[2][512*128]; // bf16 hi of gW^T, [chunk8][n128][64k]
__device__ unsigned short g_gwl[2][512*128];

__device__ __forceinline__ unsigned fmap(float f) {
    unsigned b = __float_as_uint(f);
    return b ^ ((unsigned)((int)b >> 31) | 0x80000000u);
}
__device__ __forceinline__ uint32_t smem_u32(const void* p) {
    uint32_t a;
    asm("{ .reg .u64 t; cvta.to.shared.u64 t, %1; cvt.u32.u64 %0, t; }" : "=r"(a) : "l"(p));
    return a;
}
__device__ __forceinline__ void mma_bf16(float* c, const uint32_t* a,
                                         uint32_t b0, uint32_t b1) {
    asm("mma.sync.aligned.m16n8k16.row.col.f32.bf16.bf16.f32 "
        "{%0,%1,%2,%3}, {%4,%5,%6,%7}, {%8,%9}, {%0,%1,%2,%3};"
        : "+f"(c[0]), "+f"(c[1]), "+f"(c[2]), "+f"(c[3])
        : "r"(a[0]), "r"(a[1]), "r"(a[2]), "r"(a[3]), "r"(b0), "r"(b1));
}
__device__ __forceinline__ void mma_f16f32(float* c, const uint32_t* a,
                                           uint32_t b0, uint32_t b1) {
    asm("mma.sync.aligned.m16n8k16.row.col.f32.f16.f16.f32 "
        "{%0,%1,%2,%3}, {%4,%5,%6,%7}, {%8,%9}, {%0,%1,%2,%3};"
        : "+f"(c[0]), "+f"(c[1]), "+f"(c[2]), "+f"(c[3])
        : "r"(a[0]), "r"(a[1]), "r"(a[2]), "r"(a[3]), "r"(b0), "r"(b1));
}
__device__ __forceinline__ void ldsm4(uint32_t* r, uint32_t addr) {
    asm volatile("ldmatrix.sync.aligned.m8n8.x4.shared.b16 {%0,%1,%2,%3}, [%4];"
        : "=r"(r[0]), "=r"(r[1]), "=r"(r[2]), "=r"(r[3]) : "r"(addr));
}
__device__ __forceinline__ void bf16split(float h, float h1, uint32_t& hi, uint32_t& lo) {
    asm("cvt.rn.bf16x2.f32 %0, %1, %2;" : "=r"(hi) : "f"(h1), "f"(h));
    float r0 = h - __uint_as_float(hi << 16);
    float r1 = h1 - __uint_as_float(hi & 0xffff0000u);
    asm("cvt.rn.bf16x2.f32 %0, %1, %2;" : "=r"(lo) : "f"(r1), "f"(r0));
}

// ------- fused prep kernels -------
__global__ void init_kernel() {
    int idx = blockIdx.x * 256 + threadIdx.x;
    if (idx < 2*NN*H) (&g_segout[0][0])[idx] = 0u;
    if (idx < 2*NN)   (&g_deg[0][0])[idx] = 0;
}

__global__ void uv_fused(const float* __restrict__ pos0, const float* __restrict__ pos1,
                         const float* __restrict__ W10, const float* __restrict__ W11,
                         const float* __restrict__ b10, const float* __restrict__ b11) {
    int g = blockIdx.x / NN, i = blockIdx.x - g*NN, ch = threadIdx.x;
    const float* pos = g ? pos1 : pos0;
    const float* W1  = g ? W11 : W10;
    const float* bb  = g ? b11 : b10;
    float p0 = pos[i*3+0], p1 = pos[i*3+1], p2 = pos[i*3+2];
    float c = p0*W1[3*H+ch] + p1*W1[4*H+ch] + p2*W1[5*H+ch];
    float a = p0*W1[0*H+ch] + p1*W1[1*H+ch] + p2*W1[2*H+ch] + c + bb[ch];
    g_a[g][i*H+ch] = a;
    g_c[g][i*H+ch] = c;
}

// W2 f16 split (hi + exact residual lo), transposed [chunk][n][64k]
__global__ void w2prep_fused(const float* __restrict__ W20, const float* __restrict__ W21) {
    int g = blockIdx.x >> 8;
    int idx = (blockIdx.x & 255) * 256 + threadIdx.x;  // k*256+n
    int k = idx >> 8, n = idx & 255;
    float w = (g ? W21 : W20)[idx];
    __half hb = __float2half_rn(w);
    float hf = __half2float(hb);
    __half lb = __float2half_rn(w - hf);
    int o = (k >> 6)*16384 + n*64 + (k & 63);
    g_w2h[g][o] = *(unsigned short*)&hb;
    g_w2l[g][o] = *(unsigned short*)&lb;
}

// gW [512,128] -> bf16 split, transposed [chunk8][n128][64k]
__global__ void gwprep_fused(const float* __restrict__ Wg0, const float* __restrict__ Wg1) {
    int g = blockIdx.x >> 8;
    int idx = (blockIdx.x & 255) * 256 + threadIdx.x;  // k*128+n over 65536
    int k = idx >> 7, n = idx & 127;
    float w = (g ? Wg1 : Wg0)[idx];
    __nv_bfloat16 hb = __float2bfloat16(w);
    float hf = __bfloat162float(hb);
    __nv_bfloat16 lb = __float2bfloat16(w - hf);
    int o = (k >> 6)*8192 + n*64 + (k & 63);
    g_gwh[g][o] = *(unsigned short*)&hb;
    g_gwl[g][o] = *(unsigned short*)&lb;
}

__global__ void deg_fused(const int* __restrict__ ei0, const int* __restrict__ ei1) {
    int idx = blockIdx.x * 256 + threadIdx.x;
    if (idx < 2*NE) {
        int g = idx / NE, e = idx - g*NE;
        const int* ei = g ? ei1 : ei0;
        atomicAdd(&g_deg[g][ei[NE + e]], 1);
    }
}

__global__ void scan_fused() {
    __shared__ int ss[1024];
    int g = blockIdx.x;
    int t = threadIdx.x;
    const int CH = (NN + 1023) / 1024;
    int beg = t * CH, end = beg + CH;
    if (end > NN) end = NN;
    if (beg > NN) beg = NN;
    int s = 0;
    for (int i = beg; i < end; i++) s += g_deg[g][i];
    ss[t] = s;
    __syncthreads();
    for (int off = 1; off < 1024; off <<= 1) {
        int v = (t >= off) ? ss[t-off] : 0;
        __syncthreads();
        ss[t] += v;
        __syncthreads();
    }
    int run = (t == 0) ? 0 : ss[t-1];
    for (int i = beg; i < end; i++) {
        g_offs[g][i] = run; g_cursor[g][i] = run; run += g_deg[g][i];
    }
    if (t == 1023) g_offs[g][NN] = NE;
}

__global__ void dinv_kernel() {
    int idx = blockIdx.x * 256 + threadIdx.x;
    if (idx < 2*NN) {
        int g = idx / NN, i = idx - g*NN;
        g_dinv[g][i] = rsqrtf(1.f + (float)g_deg[g][i]);
    }
}

__global__ void fill_fused(const int* __restrict__ ei0, const int* __restrict__ ei1) {
    int idx = blockIdx.x * 256 + threadIdx.x;
    if (idx < 2*NE) {
        int g = idx / NE, e = idx - g*NE;
        const int* ei = g ? ei1 : ei0;
        int d = ei[NE + e];
        int p = atomicAdd(&g_cursor[g][d], 1);
        g_ssrc[g][p] = ei[e];
        g_sdst[g][p] = d;
    }
}

// ------- pointnet: 64 edges x 256 ch per CTA, f16 2-product (W compensated) -------
#define OFF_AH 0
#define OFF_WH 9216
#define OFF_WL 46080
#define OFF_DST 82944
#define PN_SMEM 83456
#define TILES_PER_G 6250

__global__ __launch_bounds__(256, 2)
void pointnet_mma(const float* __restrict__ b20, const float* __restrict__ b21) {
    extern __shared__ char AB[];
    uint32_t abu = smem_u32(AB);
    int tid = threadIdx.x, lane = tid & 31, wid = tid >> 5;
    int g = (blockIdx.x >= TILES_PER_G) ? 1 : 0;
    int e0 = (blockIdx.x - g*TILES_PER_G) * 64;
    const float* __restrict__ b2 = g ? b21 : b20;
    int* s_dst = (int*)(AB + OFF_DST);
    if (tid < 64) s_dst[tid] = g_sdst[g][e0 + tid];

    int ge = tid >> 2, kq = (tid & 3) * 16;
    int esrc = g_ssrc[g][e0 + ge] * 256;
    int edst = g_sdst[g][e0 + ge] * 256;
    const float* __restrict__ Aa = g_a[g];
    const float* __restrict__ Cc = g_c[g];

    int eg = wid >> 2, cg = wid & 3;
    int qrow = lane >> 2;
    int qc = (lane & 3) * 2;

    uint32_t aH = abu + OFF_AH + (uint32_t)(eg*32 + (lane & 15))*144 + (lane >> 4)*16;
    uint32_t bH = abu + OFF_WH +
        (uint32_t)(cg*64 + (lane >> 4)*8 + (lane & 7))*144 + ((lane >> 3) & 1)*16;
    uint32_t bL = bH + (OFF_WL - OFF_WH);

    float acc[2][8][4];
#pragma unroll
    for (int mt = 0; mt < 2; mt++)
#pragma unroll
        for (int nt = 0; nt < 8; nt++)
#pragma unroll
            for (int j = 0; j < 4; j++) acc[mt][nt][j] = 0.f;

    for (int ck = 0; ck < 4; ck++) {
        // ---- gather + relu, single f16 digit for A ----
        {
            int k0 = ck*64 + kq;
            float4 av[4], cv[4];
#pragma unroll
            for (int q = 0; q < 4; q++) {
                av[q] = *(const float4*)(Aa + esrc + k0 + q*4);
                cv[q] = *(const float4*)(Cc + edst + k0 + q*4);
            }
            char* ph = AB + OFF_AH + (tid >> 2)*144 + kq*2;
#pragma unroll
            for (int q = 0; q < 4; q++) {
                float h0 = fmaxf(av[q].x - cv[q].x, 0.f);
                float h1 = fmaxf(av[q].y - cv[q].y, 0.f);
                float h2 = fmaxf(av[q].z - cv[q].z, 0.f);
                float h3 = fmaxf(av[q].w - cv[q].w, 0.f);
                uint32_t hi0, hi1;
                asm("cvt.rn.f16x2.f32 %0, %1, %2;" : "=r"(hi0) : "f"(h1), "f"(h0));
                asm("cvt.rn.f16x2.f32 %0, %1, %2;" : "=r"(hi1) : "f"(h3), "f"(h2));
                *(uint32_t*)(ph + q*8)     = hi0;
                *(uint32_t*)(ph + q*8 + 4) = hi1;
            }
        }
        // ---- stream W chunk [n][64] hi+lo (f16) ----
        {
            const uint4* gh4 = (const uint4*)(g_w2h[g] + ck*16384);
            const uint4* gl4 = (const uint4*)(g_w2l[g] + ck*16384);
#pragma unroll
            for (int i = 0; i < 8; i++) {
                int idx = tid + i*256;
                int row = idx >> 3, q = idx & 7;
                *(uint4*)(AB + OFF_WH + row*144 + q*16) = gh4[idx];
                *(uint4*)(AB + OFF_WL + row*144 + q*16) = gl4[idx];
            }
        }
        __syncthreads();

        // ---- MMA: 2 f16 products (A*W_hi, A*W_lo), f32 accum ----
#pragma unroll
        for (int kk = 0; kk < 4; kk++) {
            uint32_t ko = kk*32;
            uint32_t bh[4][4], bl[4][4];
#pragma unroll
            for (int p = 0; p < 4; p++) {
                ldsm4(bh[p], bH + p*(16*144) + ko);
                ldsm4(bl[p], bL + p*(16*144) + ko);
            }
#pragma unroll
            for (int mt = 0; mt < 2; mt++) {
                uint32_t ah[4];
                ldsm4(ah, aH + mt*(16*144) + ko);
#pragma unroll
                for (int p = 0; p < 4; p++) {
                    mma_f16f32(acc[mt][2*p],   ah, bh[p][0], bh[p][1]);
                    mma_f16f32(acc[mt][2*p+1], ah, bh[p][2], bh[p][3]);
                    mma_f16f32(acc[mt][2*p],   ah, bl[p][0], bl[p][1]);
                    mma_f16f32(acc[mt][2*p+1], ah, bl[p][2], bl[p][3]);
                }
            }
        }
        __syncthreads();
    }

    float* buf = (float*)AB;
#pragma unroll
    for (int mt = 0; mt < 2; mt++) {
        int row = eg*32 + mt*16 + qrow;
#pragma unroll
        for (int nt = 0; nt < 8; nt++) {
            int col = cg*64 + nt*8 + qc;
            buf[row*257 + col]       = acc[mt][nt][0];
            buf[row*257 + col + 1]   = acc[mt][nt][1];
            buf[(row+8)*257 + col]   = acc[mt][nt][2];
            buf[(row+8)*257 + col+1] = acc[mt][nt][3];
        }
    }
    __syncthreads();
    {
        unsigned* __restrict__ seg = &g_segout[g][0];
        int gch = tid;
        float bias = b2[gch];
        int cur = s_dst[0];
        float mx = buf[gch];
        for (int q = 1; q < 64; q++) {
            int d = s_dst[q];
            float v = buf[q*257 + gch];
            if (d != cur) {
                atomicMax(&seg[cur*256 + gch], fmap(mx + bias));
                cur = d; mx = v;
            } else mx = fmaxf(mx, v);
        }
        atomicMax(&seg[cur*256 + gch], fmap(mx + bias));
    }
}

// ------- xw via HMMA: [NN,512]@[512,128] per graph, 3-term bf16 -------
#define XOFF_AH 0
#define XOFF_AL 18432
#define XOFF_WH 36864
#define XOFF_WL 55296
#define XW_SMEM 73728
#define XW_TILES 157

__global__ __launch_bounds__(256, 2)
void xw_mma() {
    extern __shared__ char AB[];
    uint32_t abu = smem_u32(AB);
    int tid = threadIdx.x, lane = tid & 31, wid = tid >> 5;
    int g = (blockIdx.x >= XW_TILES) ? 1 : 0;
    int row0 = (blockIdx.x - g*XW_TILES) * 128;

    int grow = tid >> 1, kh = (tid & 1) * 32;
    int ar = row0 + grow; if (ar > NN-1) ar = NN-1;

    int eg = wid >> 1, cg = wid & 1;
    int qrow = lane >> 2;
    int qc = (lane & 3) * 2;

    uint32_t aH = abu + XOFF_AH + (uint32_t)(eg*32 + (lane & 15))*144 + (lane >> 4)*16;
    uint32_t aL = aH + (XOFF_AL - XOFF_AH);
    uint32_t bH = abu + XOFF_WH +
        (uint32_t)(cg*64 + (lane >> 4)*8 + (lane & 7))*144 + ((lane >> 3) & 1)*16;
    uint32_t bL = bH + (XOFF_WL - XOFF_WH);

    float acc[2][8][4];
#pragma unroll
    for (int mt = 0; mt < 2; mt++)
#pragma unroll
        for (int nt = 0; nt < 8; nt++)
#pragma unroll
            for (int j = 0; j < 4; j++) acc[mt][nt][j] = 0.f;

    for (int ck = 0; ck < 8; ck++) {
        {
            int kbase = ck*64 + kh;
            const unsigned* sp = (kbase < 256) ? &g_segout[0][ar*256 + kbase]
                                               : &g_segout[1][ar*256 + kbase - 256];
            char* ph = AB + XOFF_AH + grow*144 + kh*2;
            char* pl = AB + XOFF_AL + grow*144 + kh*2;
#pragma unroll
            for (int q = 0; q < 8; q++) {
                uint4 u = *(const uint4*)(sp + q*4);
                float h0 = (u.x > 0x80000000u) ? __uint_as_float(u.x ^ 0x80000000u) : 0.f;
                float h1 = (u.y > 0x80000000u) ? __uint_as_float(u.y ^ 0x80000000u) : 0.f;
                float h2 = (u.z > 0x80000000u) ? __uint_as_float(u.z ^ 0x80000000u) : 0.f;
                float h3 = (u.w > 0x80000000u) ? __uint_as_float(u.w ^ 0x80000000u) : 0.f;
                uint32_t hi0, hi1, lo0, lo1;
                bf16split(h0, h1, hi0, lo0);
                bf16split(h2, h3, hi1, lo1);
                *(uint32_t*)(ph + q*8)     = hi0;
                *(uint32_t*)(ph + q*8 + 4) = hi1;
                *(uint32_t*)(pl + q*8)     = lo0;
                *(uint32_t*)(pl + q*8 + 4) = lo1;
            }
        }
        {
            const uint4* gh4 = (const uint4*)(g_gwh[g] + ck*8192);
            const uint4* gl4 = (const uint4*)(g_gwl[g] + ck*8192);
#pragma unroll
            for (int i = 0; i < 4; i++) {
                int idx = tid + i*256;
                int row = idx >> 3, q = idx & 7;
                *(uint4*)(AB + XOFF_WH + row*144 + q*16) = gh4[idx];
                *(uint4*)(AB + XOFF_WL + row*144 + q*16) = gl4[idx];
            }
        }
        __syncthreads();

#pragma unroll
        for (int kk = 0; kk < 4; kk++) {
            uint32_t ko = kk*32;
            uint32_t bh[4][4], bl[4][4];
#pragma unroll
            for (int p = 0; p < 4; p++) {
                ldsm4(bh[p], bH + p*(16*144) + ko);
                ldsm4(bl[p], bL + p*(16*144) + ko);
            }
#pragma unroll
            for (int mt = 0; mt < 2; mt++) {
                uint32_t ah[4];
                ldsm4(ah, aH + mt*(16*144) + ko);
#pragma unroll
                for (int p = 0; p < 4; p++) {
                    mma_bf16(acc[mt][2*p],   ah, bh[p][0], bh[p][1]);
                    mma_bf16(acc[mt][2*p+1], ah, bh[p][2], bh[p][3]);
                }
            }
#pragma unroll
            for (int mt = 0; mt < 2; mt++) {
                uint32_t al[4];
                ldsm4(al, aL + mt*(16*144) + ko);
#pragma unroll
                for (int p = 0; p < 4; p++) {
                    mma_bf16(acc[mt][2*p],   al, bh[p][0], bh[p][1]);
                    mma_bf16(acc[mt][2*p+1], al, bh[p][2], bh[p][3]);
                }
            }
#pragma unroll
            for (int mt = 0; mt < 2; mt++) {
                uint32_t ah2[4];
                ldsm4(ah2, aH + mt*(16*144) + ko);
#pragma unroll
                for (int p = 0; p < 4; p++) {
                    mma_bf16(acc[mt][2*p],   ah2, bl[p][0], bl[p][1]);
                    mma_bf16(acc[mt][2*p+1], ah2, bl[p][2], bl[p][3]);
                }
            }
        }
        __syncthreads();
    }

    float* __restrict__ xw = g_xw[g];
#pragma unroll
    for (int mt = 0; mt < 2; mt++) {
        int r0 = row0 + eg*32 + mt*16 + qrow;
#pragma unroll
        for (int nt = 0; nt < 8; nt++) {
            int col = cg*64 + nt*8 + qc;
            if (r0 < NN)
                *(float2*)(xw + r0*128 + col) = make_float2(acc[mt][nt][0], acc[mt][nt][1]);
            if (r0 + 8 < NN)
                *(float2*)(xw + (r0+8)*128 + col) = make_float2(acc[mt][nt][2], acc[mt][nt][3]);
        }
    }
}

// ------- agg: one block per node, both graphs, float2 channels -------
__global__ void agg_paired(const float* __restrict__ gb0, const float* __restrict__ gb1) {
    int i = blockIdx.x;
    int t = threadIdx.x;
    int g = t >> 6;
    int ch = (t & 63) * 2;
    const float* __restrict__ xw = g_xw[g];
    const float* __restrict__ bias = g ? gb1 : gb0;
    float di = g_dinv[g][i];
    int beg = g_offs[g][i], end = g_offs[g][i+1];
    float ax = 0.f, ay = 0.f;
    for (int e = beg; e < end; e++) {
        int s = g_ssrc[g][e];
        float2 v = *(const float2*)(xw + s*128 + ch);
        float dv = g_dinv[g][s];
        ax += v.x * dv; ay += v.y * dv;
    }
    float2 self = *(const float2*)(xw + i*128 + ch);
    float d2 = di*di;
    float vx = di*ax + self.x*d2 + bias[ch];
    float vy = di*ay + self.y*d2 + bias[ch+1];
    *(float2*)(&g_h2[i*256 + g*128 + ch]) = make_float2(fmaxf(vx, 0.f), fmaxf(vy, 0.f));
}

__global__ __launch_bounds__(256)
void c3cls_kernel(const float* __restrict__ Wc, const float* __restrict__ bc,
                  const float* __restrict__ clsW) {
    __shared__ float s_a[64*16];
    __shared__ float4 s_b[16*32];
    __shared__ float red[256];
    int tid = threadIdx.x, tx = tid & 31, ty = tid >> 5;
    int row0 = blockIdx.x * 64;
    float acc[8][4];
#pragma unroll
    for (int i = 0; i < 8; i++)
#pragma unroll
        for (int j = 0; j < 4; j++) acc[i][j] = 0.f;
    int lr = tid >> 2, lk = (tid & 3) * 4;
    int ar = row0 + lr; if (ar > NN-1) ar = NN-1;
    const float4* B4 = (const float4*)Wc;
    for (int k0 = 0; k0 < 256; k0 += 16) {
        float4 av = *(const float4*)(g_h2 + ar*256 + k0 + lk);
        float4 bv[2];
#pragma unroll
        for (int q = 0; q < 2; q++) {
            int idx = tid + q*256;
            bv[q] = B4[(k0 + (idx >> 5))*32 + (idx & 31)];
        }
        __syncthreads();
        *(float4*)(s_a + lr*16 + lk) = av;
#pragma unroll
        for (int q = 0; q < 2; q++) s_b[tid + q*256] = bv[q];
        __syncthreads();
#pragma unroll
        for (int kk = 0; kk < 16; kk++) {
            float4 b = s_b[kk*32 + tx];
#pragma unroll
            for (int i = 0; i < 8; i++) {
                float a = s_a[(ty*8 + i)*16 + kk];
                acc[i][0] += a*b.x; acc[i][1] += a*b.y;
                acc[i][2] += a*b.z; acc[i][3] += a*b.w;
            }
        }
    }
    float sum0 = 0.f, sum1 = 0.f, sum2 = 0.f;
#pragma unroll
    for (int i = 0; i < 8; i++) {
        int r = row0 + ty*8 + i;
        if (r < NN) {
#pragma unroll
            for (int jj = 0; jj < 4; jj++) {
                float v = fmaxf(acc[i][jj] + bc[tx*4 + jj], 0.f);
                const float* w = clsW + (r*128 + tx*4 + jj)*3;
                sum0 += v*w[0]; sum1 += v*w[1]; sum2 += v*w[2];
            }
        }
    }
    float sums[3] = {sum0, sum1, sum2};
#pragma unroll
    for (int r3 = 0; r3 < 3; r3++) {
        red[tid] = sums[r3];
        __syncthreads();
        for (int s = 128; s > 0; s >>= 1) {
            if (tid < s) red[tid] += red[tid + s];
            __syncthreads();
        }
        if (tid == 0) g_partial[blockIdx.x*3 + r3] = red[0];
        __syncthreads();
    }
}

__global__ void final_kernel(const float* __restrict__ clsb, float* __restrict__ out, int nblk) {
    int r = threadIdx.x;
    if (r < 3) {
        double s = (double)clsb[r];
        for (int i = 0; i < nblk; i++) s += (double)g_partial[i*3 + r];
        out[r] = (float)s;
    }
}

extern "C" void kernel_launch(void* const* d_in, const int* in_sizes, int n_in,
                              void* d_out, int out_size) {
    const float *pos[2]={0,0}, *W1[2]={0,0}, *b1[2]={0,0}, *W2[2]={0,0}, *b2[2]={0,0};
    const float *gW[2]={0,0}, *gb[2]={0,0}, *cW=0, *cb=0, *clsW=0, *clsb=0;
    const int *ei[2]={0,0};
    int npos=0, nei=0, nw1=0, n256=0, n64k=0, n128=0;
    for (int i = 0; i < n_in; i++) {
        int sz = in_sizes[i];
        const float* f = (const float*)d_in[i];
        if (sz == 3*NN)            { if (npos<2) pos[npos++] = f; }
        else if (sz == 2*NE)       { if (nei<2)  ei[nei++] = (const int*)d_in[i]; }
        else if (sz == 6*H)        { if (nw1<2)  W1[nw1++] = f; }
        else if (sz == H)          { int j=n256++; if(j==0)b1[0]=f; else if(j==1)b2[0]=f;
                                     else if(j==2)b1[1]=f; else if(j==3)b2[1]=f; }
        else if (sz == H*H)        { int j=n64k++; if(j<2) W2[j]=f; else if(j<4) gW[j-2]=f; }
        else if (sz == H/2)        { int j=n128++; if(j<2) gb[j]=f; else cb=f; }
        else if (sz == H*(H/2))    { cW = f; }
        else if (sz == NN*(H/2)*3) { clsW = f; }
        else if (sz == 3)          { clsb = f; }
    }

    static bool attr_done = false;
    if (!attr_done) {
        cudaFuncSetAttribute(pointnet_mma, cudaFuncAttributeMaxDynamicSharedMemorySize, PN_SMEM);
        cudaFuncSetAttribute(xw_mma, cudaFuncAttributeMaxDynamicSharedMemorySize, XW_SMEM);
        attr_done = true;
    }

    init_kernel<<<(2*NN*H + 255)/256, 256>>>();
    uv_fused<<<2*NN, 256>>>(pos[0], pos[1], W1[0], W1[1], b1[0], b1[1]);
    w2prep_fused<<<512, 256>>>(W2[0], W2[1]);
    gwprep_fused<<<512, 256>>>(gW[0], gW[1]);
    deg_fused<<<(2*NE + 255)/256, 256>>>(ei[0], ei[1]);
    scan_fused<<<2, 1024>>>();
    fill_fused<<<(2*NE + 255)/256, 256>>>(ei[0], ei[1]);
    dinv_kernel<<<(2*NN + 255)/256, 256>>>();
    pointnet_mma<<<2*TILES_PER_G, 256, PN_SMEM>>>(b2[0], b2[1]);
    xw_mma<<<2*XW_TILES, 256, XW_SMEM>>>();
    agg_paired<<<NN, 128>>>(gb[0], gb[1]);
    int nblk = (NN + 63)/64;
    c3cls_kernel<<<nblk, 256>>>(cW, cb, clsW);
    final_kernel<<<1, 32>>>(clsb, (float*)d_out, nblk);
}

// round 15
// speedup vs baseline: 2.9581x; 1.0567x over previous
#include <cuda_runtime.h>
#include <cuda_bf16.h>
#include <cuda_fp16.h>
#include <cstdint>

#define NN 20000
#define NE 400000
#define H  256

// ------- static scratch (allocations forbidden) -------
__device__ float    g_a[2][NN*H];
__device__ float    g_c[2][NN*H];
__device__ unsigned g_segout[2][NN*H];   // mapped-uint running max, 0 = empty
__device__ float    g_xw[2][NN*128];
__device__ float    g_h2[NN*256];
__device__ int      g_deg[2][NN];
__device__ int      g_offs[2][NN+1];
__device__ int      g_cursor[2][NN];
__device__ int      g_ssrc[2][NE];
__device__ int      g_sdst[2][NE];
__device__ float    g_dinv[2][NN];
__device__ float    g_partial[1024*3];
__device__ unsigned short g_w2h[2][H*H];  // f16 hi of W2^T, [chunk][n][64k]
__device__ unsigned char  g_w2l8[2][H*H]; // e5m2 of (residual * 2^10)
__device__ unsigned short g_gwh[2][512*128]; // bf16 hi of gW^T, [chunk8][n128][64k]
__device__ unsigned short g_gwl[2][512*128];

__device__ __forceinline__ unsigned fmap(float f) {
    unsigned b = __float_as_uint(f);
    return b ^ ((unsigned)((int)b >> 31) | 0x80000000u);
}
__device__ __forceinline__ uint32_t smem_u32(const void* p) {
    uint32_t a;
    asm("{ .reg .u64 t; cvta.to.shared.u64 t, %1; cvt.u32.u64 %0, t; }" : "=r"(a) : "l"(p));
    return a;
}
__device__ __forceinline__ void mma_bf16(float* c, const uint32_t* a,
                                         uint32_t b0, uint32_t b1) {
    asm("mma.sync.aligned.m16n8k16.row.col.f32.bf16.bf16.f32 "
        "{%0,%1,%2,%3}, {%4,%5,%6,%7}, {%8,%9}, {%0,%1,%2,%3};"
        : "+f"(c[0]), "+f"(c[1]), "+f"(c[2]), "+f"(c[3])
        : "r"(a[0]), "r"(a[1]), "r"(a[2]), "r"(a[3]), "r"(b0), "r"(b1));
}
__device__ __forceinline__ void mma_f16f32(float* c, const uint32_t* a,
                                           uint32_t b0, uint32_t b1) {
    asm("mma.sync.aligned.m16n8k16.row.col.f32.f16.f16.f32 "
        "{%0,%1,%2,%3}, {%4,%5,%6,%7}, {%8,%9}, {%0,%1,%2,%3};"
        : "+f"(c[0]), "+f"(c[1]), "+f"(c[2]), "+f"(c[3])
        : "r"(a[0]), "r"(a[1]), "r"(a[2]), "r"(a[3]), "r"(b0), "r"(b1));
}
__device__ __forceinline__ void ldsm4(uint32_t* r, uint32_t addr) {
    asm volatile("ldmatrix.sync.aligned.m8n8.x4.shared.b16 {%0,%1,%2,%3}, [%4];"
        : "=r"(r[0]), "=r"(r[1]), "=r"(r[2]), "=r"(r[3]) : "r"(addr));
}
__device__ __forceinline__ void bf16split(float h, float h1, uint32_t& hi, uint32_t& lo) {
    asm("cvt.rn.bf16x2.f32 %0, %1, %2;" : "=r"(hi) : "f"(h1), "f"(h));
    float r0 = h - __uint_as_float(hi << 16);
    float r1 = h1 - __uint_as_float(hi & 0xffff0000u);
    asm("cvt.rn.bf16x2.f32 %0, %1, %2;" : "=r"(lo) : "f"(r1), "f"(r0));
}
__device__ __forceinline__ uint32_t prmt0(uint32_t a, uint32_t sel) {
    uint32_t d;
    asm("prmt.b32 %0, %1, 0, %2;" : "=r"(d) : "r"(a), "r"(sel));
    return d;
}
__device__ __forceinline__ uint32_t hmul2c(uint32_t a) { // f16x2 * 2^-10
    uint32_t d;
    asm("mul.f16x2 %0, %1, %2;" : "=r"(d) : "r"(a), "r"(0x14001400u));
    return d;
}

// ------- fused prep kernels -------
__global__ void uv_fused(const float* __restrict__ pos0, const float* __restrict__ pos1,
                         const float* __restrict__ W10, const float* __restrict__ W11,
                         const float* __restrict__ b10, const float* __restrict__ b11) {
    // fused: clear segout (grid covers exactly 2*NN*H threads)
    (&g_segout[0][0])[blockIdx.x*256 + threadIdx.x] = 0u;
    int g = blockIdx.x / NN, i = blockIdx.x - g*NN, ch = threadIdx.x;
    const float* pos = g ? pos1 : pos0;
    const float* W1  = g ? W11 : W10;
    const float* bb  = g ? b11 : b10;
    float p0 = pos[i*3+0], p1 = pos[i*3+1], p2 = pos[i*3+2];
    float c = p0*W1[3*H+ch] + p1*W1[4*H+ch] + p2*W1[5*H+ch];
    float a = p0*W1[0*H+ch] + p1*W1[1*H+ch] + p2*W1[2*H+ch] + c + bb[ch];
    g_a[g][i*H+ch] = a;
    g_c[g][i*H+ch] = c;
}

// W2: f16 hi + e5m2 lo (residual*2^10), transposed [chunk][n][64k]; also clears deg
__global__ void w2prep_fused(const float* __restrict__ W20, const float* __restrict__ W21) {
    int gid = blockIdx.x * 256 + threadIdx.x;
    if (gid < 2*NN) (&g_deg[0][0])[gid] = 0;
    int g = blockIdx.x >> 8;
    int idx = (blockIdx.x & 255) * 256 + threadIdx.x;  // k*256+n
    int k = idx >> 8, n = idx & 255;
    float w = (g ? W21 : W20)[idx];
    __half hb = __float2half_rn(w);
    float r = (w - __half2float(hb)) * 1024.f;
    __half rb = __float2half_rn(r);
    unsigned short rbits = *(unsigned short*)&rb;
    unsigned char lo8 = (unsigned char)(((unsigned)rbits + 0x7Fu + ((rbits >> 8) & 1u)) >> 8);
    int o = (k >> 6)*16384 + n*64 + (k & 63);
    g_w2h[g][o]  = *(unsigned short*)&hb;
    g_w2l8[g][o] = lo8;
}

// gW [512,128] -> bf16 split, transposed [chunk8][n128][64k]
__global__ void gwprep_fused(const float* __restrict__ Wg0, const float* __restrict__ Wg1) {
    int g = blockIdx.x >> 8;
    int idx = (blockIdx.x & 255) * 256 + threadIdx.x;
    int k = idx >> 7, n = idx & 127;
    float w = (g ? Wg1 : Wg0)[idx];
    __nv_bfloat16 hb = __float2bfloat16(w);
    float hf = __bfloat162float(hb);
    __nv_bfloat16 lb = __float2bfloat16(w - hf);
    int o = (k >> 6)*8192 + n*64 + (k & 63);
    g_gwh[g][o] = *(unsigned short*)&hb;
    g_gwl[g][o] = *(unsigned short*)&lb;
}

__global__ void deg_fused(const int* __restrict__ ei0, const int* __restrict__ ei1) {
    int idx = blockIdx.x * 256 + threadIdx.x;
    if (idx < 2*NE) {
        int g = idx / NE, e = idx - g*NE;
        const int* ei = g ? ei1 : ei0;
        atomicAdd(&g_deg[g][ei[NE + e]], 1);
    }
}

__global__ void scan_fused() {
    __shared__ int ss[1024];
    int g = blockIdx.x;
    int t = threadIdx.x;
    const int CH = (NN + 1023) / 1024;
    int beg = t * CH, end = beg + CH;
    if (end > NN) end = NN;
    if (beg > NN) beg = NN;
    int s = 0;
    for (int i = beg; i < end; i++) s += g_deg[g][i];
    ss[t] = s;
    __syncthreads();
    for (int off = 1; off < 1024; off <<= 1) {
        int v = (t >= off) ? ss[t-off] : 0;
        __syncthreads();
        ss[t] += v;
        __syncthreads();
    }
    int run = (t == 0) ? 0 : ss[t-1];
    for (int i = beg; i < end; i++) {
        int d = g_deg[g][i];
        g_offs[g][i] = run; g_cursor[g][i] = run; run += d;
        g_dinv[g][i] = rsqrtf(1.f + (float)d);   // fused dinv
    }
    if (t == 1023) g_offs[g][NN] = NE;
}

__global__ void fill_fused(const int* __restrict__ ei0, const int* __restrict__ ei1) {
    int idx = blockIdx.x * 256 + threadIdx.x;
    if (idx < 2*NE) {
        int g = idx / NE, e = idx - g*NE;
        const int* ei = g ? ei1 : ei0;
        int d = ei[NE + e];
        int p = atomicAdd(&g_cursor[g][d], 1);
        g_ssrc[g][p] = ei[e];
        g_sdst[g][p] = d;
    }
}

// ------- pointnet: 64 edges x 256 ch per CTA, f16 2-product, e5m2 W-lo -------
#define OFF_AH 0
#define OFF_WH 9216
#define OFF_WL 46080
#define OFF_DST 82944
#define PN_SMEM 83456
#define TILES_PER_G 6250

__global__ __launch_bounds__(256, 2)
void pointnet_mma(const float* __restrict__ b20, const float* __restrict__ b21) {
    extern __shared__ char AB[];
    uint32_t abu = smem_u32(AB);
    int tid = threadIdx.x, lane = tid & 31, wid = tid >> 5;
    int g = (blockIdx.x >= TILES_PER_G) ? 1 : 0;
    int e0 = (blockIdx.x - g*TILES_PER_G) * 64;
    const float* __restrict__ b2 = g ? b21 : b20;
    int* s_dst = (int*)(AB + OFF_DST);
    if (tid < 64) s_dst[tid] = g_sdst[g][e0 + tid];

    int ge = tid >> 2, kq = (tid & 3) * 16;
    int esrc = g_ssrc[g][e0 + ge] * 256;
    int edst = g_sdst[g][e0 + ge] * 256;
    const float* __restrict__ Aa = g_a[g];
    const float* __restrict__ Cc = g_c[g];

    int eg = wid >> 2, cg = wid & 3;
    int qrow = lane >> 2;
    int qc = (lane & 3) * 2;

    uint32_t aH = abu + OFF_AH + (uint32_t)(eg*32 + (lane & 15))*144 + (lane >> 4)*16;
    uint32_t bH = abu + OFF_WH +
        (uint32_t)(cg*64 + (lane >> 4)*8 + (lane & 7))*144 + ((lane >> 3) & 1)*16;
    uint32_t bL = bH + (OFF_WL - OFF_WH);

    float acc[2][8][4];
#pragma unroll
    for (int mt = 0; mt < 2; mt++)
#pragma unroll
        for (int nt = 0; nt < 8; nt++)
#pragma unroll
            for (int j = 0; j < 4; j++) acc[mt][nt][j] = 0.f;

    for (int ck = 0; ck < 4; ck++) {
        // ---- gather + relu, single f16 digit for A ----
        {
            int k0 = ck*64 + kq;
            float4 av[4], cv[4];
#pragma unroll
            for (int q = 0; q < 4; q++) {
                av[q] = *(const float4*)(Aa + esrc + k0 + q*4);
                cv[q] = *(const float4*)(Cc + edst + k0 + q*4);
            }
            char* ph = AB + OFF_AH + (tid >> 2)*144 + kq*2;
#pragma unroll
            for (int q = 0; q < 4; q++) {
                float h0 = fmaxf(av[q].x - cv[q].x, 0.f);
                float h1 = fmaxf(av[q].y - cv[q].y, 0.f);
                float h2 = fmaxf(av[q].z - cv[q].z, 0.f);
                float h3 = fmaxf(av[q].w - cv[q].w, 0.f);
                uint32_t hi0, hi1;
                asm("cvt.rn.f16x2.f32 %0, %1, %2;" : "=r"(hi0) : "f"(h1), "f"(h0));
                asm("cvt.rn.f16x2.f32 %0, %1, %2;" : "=r"(hi1) : "f"(h3), "f"(h2));
                *(uint32_t*)(ph + q*8)     = hi0;
                *(uint32_t*)(ph + q*8 + 4) = hi1;
            }
        }
        // ---- stream W chunk: hi f16 direct, lo e5m2 expand (shift-exact) ----
        {
            const uint4* gh4 = (const uint4*)(g_w2h[g] + ck*16384);
#pragma unroll
            for (int i = 0; i < 8; i++) {
                int idx = tid + i*256;
                int row = idx >> 3, q = idx & 7;
                *(uint4*)(AB + OFF_WH + row*144 + q*16) = gh4[idx];
            }
            const uint4* gl8 = (const uint4*)(g_w2l8[g] + ck*16384);
#pragma unroll
            for (int i = 0; i < 4; i++) {
                int row = (tid >> 2) + i*64, part = tid & 3;
                uint4 s4 = gl8[row*4 + part];
                uint32_t s[4] = {s4.x, s4.y, s4.z, s4.w};
                uint32_t o[8];
#pragma unroll
                for (int j = 0; j < 4; j++) {
                    o[2*j]   = hmul2c(prmt0(s[j], 0x1404u));
                    o[2*j+1] = hmul2c(prmt0(s[j], 0x3424u));
                }
                char* dst = AB + OFF_WL + row*144 + part*32;
                *(uint4*)dst        = make_uint4(o[0], o[1], o[2], o[3]);
                *(uint4*)(dst + 16) = make_uint4(o[4], o[5], o[6], o[7]);
            }
        }
        __syncthreads();

        // ---- MMA: 2 f16 products (A*W_hi, A*W_lo), f32 accum ----
#pragma unroll
        for (int kk = 0; kk < 4; kk++) {
            uint32_t ko = kk*32;
            uint32_t bh[4][4], bl[4][4];
#pragma unroll
            for (int p = 0; p < 4; p++) {
                ldsm4(bh[p], bH + p*(16*144) + ko);
                ldsm4(bl[p], bL + p*(16*144) + ko);
            }
#pragma unroll
            for (int mt = 0; mt < 2; mt++) {
                uint32_t ah[4];
                ldsm4(ah, aH + mt*(16*144) + ko);
#pragma unroll
                for (int p = 0; p < 4; p++) {
                    mma_f16f32(acc[mt][2*p],   ah, bh[p][0], bh[p][1]);
                    mma_f16f32(acc[mt][2*p+1], ah, bh[p][2], bh[p][3]);
                    mma_f16f32(acc[mt][2*p],   ah, bl[p][0], bl[p][1]);
                    mma_f16f32(acc[mt][2*p+1], ah, bl[p][2], bl[p][3]);
                }
            }
        }
        __syncthreads();
    }

    float* buf = (float*)AB;
#pragma unroll
    for (int mt = 0; mt < 2; mt++) {
        int row = eg*32 + mt*16 + qrow;
#pragma unroll
        for (int nt = 0; nt < 8; nt++) {
            int col = cg*64 + nt*8 + qc;
            buf[row*257 + col]       = acc[mt][nt][0];
            buf[row*257 + col + 1]   = acc[mt][nt][1];
            buf[(row+8)*257 + col]   = acc[mt][nt][2];
            buf[(row+8)*257 + col+1] = acc[mt][nt][3];
        }
    }
    __syncthreads();
    {
        unsigned* __restrict__ seg = &g_segout[g][0];
        int gch = tid;
        float bias = b2[gch];
        int cur = s_dst[0];
        float mx = buf[gch];
        for (int q = 1; q < 64; q++) {
            int d = s_dst[q];
            float v = buf[q*257 + gch];
            if (d != cur) {
                atomicMax(&seg[cur*256 + gch], fmap(mx + bias));
                cur = d; mx = v;
            } else mx = fmaxf(mx, v);
        }
        atomicMax(&seg[cur*256 + gch], fmap(mx + bias));
    }
}

// ------- xw via HMMA: [NN,512]@[512,128] per graph, 3-term bf16 -------
#define XOFF_AH 0
#define XOFF_AL 18432
#define XOFF_WH 36864
#define XOFF_WL 55296
#define XW_SMEM 73728
#define XW_TILES 157

__global__ __launch_bounds__(256, 2)
void xw_mma() {
    extern __shared__ char AB[];
    uint32_t abu = smem_u32(AB);
    int tid = threadIdx.x, lane = tid & 31, wid = tid >> 5;
    int g = (blockIdx.x >= XW_TILES) ? 1 : 0;
    int row0 = (blockIdx.x - g*XW_TILES) * 128;

    int grow = tid >> 1, kh = (tid & 1) * 32;
    int ar = row0 + grow; if (ar > NN-1) ar = NN-1;

    int eg = wid >> 1, cg = wid & 1;
    int qrow = lane >> 2;
    int qc = (lane & 3) * 2;

    uint32_t aH = abu + XOFF_AH + (uint32_t)(eg*32 + (lane & 15))*144 + (lane >> 4)*16;
    uint32_t aL = aH + (XOFF_AL - XOFF_AH);
    uint32_t bH = abu + XOFF_WH +
        (uint32_t)(cg*64 + (lane >> 4)*8 + (lane & 7))*144 + ((lane >> 3) & 1)*16;
    uint32_t bL = bH + (XOFF_WL - XOFF_WH);

    float acc[2][8][4];
#pragma unroll
    for (int mt = 0; mt < 2; mt++)
#pragma unroll
        for (int nt = 0; nt < 8; nt++)
#pragma unroll
            for (int j = 0; j < 4; j++) acc[mt][nt][j] = 0.f;

    for (int ck = 0; ck < 8; ck++) {
        {
            int kbase = ck*64 + kh;
            const unsigned* sp = (kbase < 256) ? &g_segout[0][ar*256 + kbase]
                                               : &g_segout[1][ar*256 + kbase - 256];
            char* ph = AB + XOFF_AH + grow*144 + kh*2;
            char* pl = AB + XOFF_AL + grow*144 + kh*2;
#pragma unroll
            for (int q = 0; q < 8; q++) {
                uint4 u = *(const uint4*)(sp + q*4);
                float h0 = (u.x > 0x80000000u) ? __uint_as_float(u.x ^ 0x80000000u) : 0.f;
                float h1 = (u.y > 0x80000000u) ? __uint_as_float(u.y ^ 0x80000000u) : 0.f;
                float h2 = (u.z > 0x80000000u) ? __uint_as_float(u.z ^ 0x80000000u) : 0.f;
                float h3 = (u.w > 0x80000000u) ? __uint_as_float(u.w ^ 0x80000000u) : 0.f;
                uint32_t hi0, hi1, lo0, lo1;
                bf16split(h0, h1, hi0, lo0);
                bf16split(h2, h3, hi1, lo1);
                *(uint32_t*)(ph + q*8)     = hi0;
                *(uint32_t*)(ph + q*8 + 4) = hi1;
                *(uint32_t*)(pl + q*8)     = lo0;
                *(uint32_t*)(pl + q*8 + 4) = lo1;
            }
        }
        {
            const uint4* gh4 = (const uint4*)(g_gwh[g] + ck*8192);
            const uint4* gl4 = (const uint4*)(g_gwl[g] + ck*8192);
#pragma unroll
            for (int i = 0; i < 4; i++) {
                int idx = tid + i*256;
                int row = idx >> 3, q = idx & 7;
                *(uint4*)(AB + XOFF_WH + row*144 + q*16) = gh4[idx];
                *(uint4*)(AB + XOFF_WL + row*144 + q*16) = gl4[idx];
            }
        }
        __syncthreads();

#pragma unroll
        for (int kk = 0; kk < 4; kk++) {
            uint32_t ko = kk*32;
            uint32_t bh[4][4], bl[4][4];
#pragma unroll
            for (int p = 0; p < 4; p++) {
                ldsm4(bh[p], bH + p*(16*144) + ko);
                ldsm4(bl[p], bL + p*(16*144) + ko);
            }
#pragma unroll
            for (int mt = 0; mt < 2; mt++) {
                uint32_t ah[4];
                ldsm4(ah, aH + mt*(16*144) + ko);
#pragma unroll
                for (int p = 0; p < 4; p++) {
                    mma_bf16(acc[mt][2*p],   ah, bh[p][0], bh[p][1]);
                    mma_bf16(acc[mt][2*p+1], ah, bh[p][2], bh[p][3]);
                }
            }
#pragma unroll
            for (int mt = 0; mt < 2; mt++) {
                uint32_t al[4];
                ldsm4(al, aL + mt*(16*144) + ko);
#pragma unroll
                for (int p = 0; p < 4; p++) {
                    mma_bf16(acc[mt][2*p],   al, bh[p][0], bh[p][1]);
                    mma_bf16(acc[mt][2*p+1], al, bh[p][2], bh[p][3]);
                }
            }
#pragma unroll
            for (int mt = 0; mt < 2; mt++) {
                uint32_t ah2[4];
                ldsm4(ah2, aH + mt*(16*144) + ko);
#pragma unroll
                for (int p = 0; p < 4; p++) {
                    mma_bf16(acc[mt][2*p],   ah2, bl[p][0], bl[p][1]);
                    mma_bf16(acc[mt][2*p+1], ah2, bl[p][2], bl[p][3]);
                }
            }
        }
        __syncthreads();
    }

    float* __restrict__ xw = g_xw[g];
#pragma unroll
    for (int mt = 0; mt < 2; mt++) {
        int r0 = row0 + eg*32 + mt*16 + qrow;
#pragma unroll
        for (int nt = 0; nt < 8; nt++) {
            int col = cg*64 + nt*8 + qc;
            if (r0 < NN)
                *(float2*)(xw + r0*128 + col) = make_float2(acc[mt][nt][0], acc[mt][nt][1]);
            if (r0 + 8 < NN)
                *(float2*)(xw + (r0+8)*128 + col) = make_float2(acc[mt][nt][2], acc[mt][nt][3]);
        }
    }
}

// ------- agg: one block per node, both graphs, float2 channels -------
__global__ void agg_paired(const float* __restrict__ gb0, const float* __restrict__ gb1) {
    int i = blockIdx.x;
    int t = threadIdx.x;
    int g = t >> 6;
    int ch = (t & 63) * 2;
    const float* __restrict__ xw = g_xw[g];
    const float* __restrict__ bias = g ? gb1 : gb0;
    float di = g_dinv[g][i];
    int beg = g_offs[g][i], end = g_offs[g][i+1];
    float ax = 0.f, ay = 0.f;
    for (int e = beg; e < end; e++) {
        int s = g_ssrc[g][e];
        float2 v = *(const float2*)(xw + s*128 + ch);
        float dv = g_dinv[g][s];
        ax += v.x * dv; ay += v.y * dv;
    }
    float2 self = *(const float2*)(xw + i*128 + ch);
    float d2 = di*di;
    float vx = di*ax + self.x*d2 + bias[ch];
    float vy = di*ay + self.y*d2 + bias[ch+1];
    *(float2*)(&g_h2[i*256 + g*128 + ch]) = make_float2(fmaxf(vx, 0.f), fmaxf(vy, 0.f));
}

__global__ __launch_bounds__(256)
void c3cls_kernel(const float* __restrict__ Wc, const float* __restrict__ bc,
                  const float* __restrict__ clsW) {
    __shared__ float s_a[64*16];
    __shared__ float4 s_b[16*32];
    __shared__ float red[256];
    int tid = threadIdx.x, tx = tid & 31, ty = tid >> 5;
    int row0 = blockIdx.x * 64;
    float acc[8][4];
#pragma unroll
    for (int i = 0; i < 8; i++)
#pragma unroll
        for (int j = 0; j < 4; j++) acc[i][j] = 0.f;
    int lr = tid >> 2, lk = (tid & 3) * 4;
    int ar = row0 + lr; if (ar > NN-1) ar = NN-1;
    const float4* B4 = (const float4*)Wc;
    for (int k0 = 0; k0 < 256; k0 += 16) {
        float4 av = *(const float4*)(g_h2 + ar*256 + k0 + lk);
        float4 bv[2];
#pragma unroll
        for (int q = 0; q < 2; q++) {
            int idx = tid + q*256;
            bv[q] = B4[(k0 + (idx >> 5))*32 + (idx & 31)];
        }
        __syncthreads();
        *(float4*)(s_a + lr*16 + lk) = av;
#pragma unroll
        for (int q = 0; q < 2; q++) s_b[tid + q*256] = bv[q];
        __syncthreads();
#pragma unroll
        for (int kk = 0; kk < 16; kk++) {
            float4 b = s_b[kk*32 + tx];
#pragma unroll
            for (int i = 0; i < 8; i++) {
                float a = s_a[(ty*8 + i)*16 + kk];
                acc[i][0] += a*b.x; acc[i][1] += a*b.y;
                acc[i][2] += a*b.z; acc[i][3] += a*b.w;
            }
        }
    }
    float sum0 = 0.f, sum1 = 0.f, sum2 = 0.f;
#pragma unroll
    for (int i = 0; i < 8; i++) {
        int r = row0 + ty*8 + i;
        if (r < NN) {
#pragma unroll
            for (int jj = 0; jj < 4; jj++) {
                float v = fmaxf(acc[i][jj] + bc[tx*4 + jj], 0.f);
                const float* w = clsW + (r*128 + tx*4 + jj)*3;
                sum0 += v*w[0]; sum1 += v*w[1]; sum2 += v*w[2];
            }
        }
    }
    float sums[3] = {sum0, sum1, sum2};
#pragma unroll
    for (int r3 = 0; r3 < 3; r3++) {
        red[tid] = sums[r3];
        __syncthreads();
        for (int s = 128; s > 0; s >>= 1) {
            if (tid < s) red[tid] += red[tid + s];
            __syncthreads();
        }
        if (tid == 0) g_partial[blockIdx.x*3 + r3] = red[0];
        __syncthreads();
    }
}

__global__ void final_kernel(const float* __restrict__ clsb, float* __restrict__ out, int nblk) {
    int r = threadIdx.x;
    if (r < 3) {
        double s = (double)clsb[r];
        for (int i = 0; i < nblk; i++) s += (double)g_partial[i*3 + r];
        out[r] = (float)s;
    }
}

extern "C" void kernel_launch(void* const* d_in, const int* in_sizes, int n_in,
                              void* d_out, int out_size) {
    const float *pos[2]={0,0}, *W1[2]={0,0}, *b1[2]={0,0}, *W2[2]={0,0}, *b2[2]={0,0};
    const float *gW[2]={0,0}, *gb[2]={0,0}, *cW=0, *cb=0, *clsW=0, *clsb=0;
    const int *ei[2]={0,0};
    int npos=0, nei=0, nw1=0, n256=0, n64k=0, n128=0;
    for (int i = 0; i < n_in; i++) {
        int sz = in_sizes[i];
        const float* f = (const float*)d_in[i];
        if (sz == 3*NN)            { if (npos<2) pos[npos++] = f; }
        else if (sz == 2*NE)       { if (nei<2)  ei[nei++] = (const int*)d_in[i]; }
        else if (sz == 6*H)        { if (nw1<2)  W1[nw1++] = f; }
        else if (sz == H)          { int j=n256++; if(j==0)b1[0]=f; else if(j==1)b2[0]=f;
                                     else if(j==2)b1[1]=f; else if(j==3)b2[1]=f; }
        else if (sz == H*H)        { int j=n64k++; if(j<2) W2[j]=f; else if(j<4) gW[j-2]=f; }
        else if (sz == H/2)        { int j=n128++; if(j<2) gb[j]=f; else cb=f; }
        else if (sz == H*(H/2))    { cW = f; }
        else if (sz == NN*(H/2)*3) { clsW = f; }
        else if (sz == 3)          { clsb = f; }
    }

    static bool attr_done = false;
    if (!attr_done) {
        cudaFuncSetAttribute(pointnet_mma, cudaFuncAttributeMaxDynamicSharedMemorySize, PN_SMEM);
        cudaFuncSetAttribute(xw_mma, cudaFuncAttributeMaxDynamicSharedMemorySize, XW_SMEM);
        attr_done = true;
    }

    uv_fused<<<2*NN, 256>>>(pos[0], pos[1], W1[0], W1[1], b1[0], b1[1]);
    w2prep_fused<<<512, 256>>>(W2[0], W2[1]);
    gwprep_fused<<<512, 256>>>(gW[0], gW[1]);
    deg_fused<<<(2*NE + 255)/256, 256>>>(ei[0], ei[1]);
    scan_fused<<<2, 1024>>>();
    fill_fused<<<(2*NE + 255)/256, 256>>>(ei[0], ei[1]);
    pointnet_mma<<<2*TILES_PER_G, 256, PN_SMEM>>>(b2[0], b2[1]);
    xw_mma<<<2*XW_TILES, 256, XW_SMEM>>>();
    agg_paired<<<NN, 128>>>(gb[0], gb[1]);
    int nblk = (NN + 63)/64;
    c3cls_kernel<<<nblk, 256>>>(cW, cb, clsW);
    final_kernel<<<1, 32>>>(clsb, (float*)d_out, nblk);
}

// round 16
// speedup vs baseline: 3.2745x; 1.1069x over previous
#include <cuda_runtime.h>
#include <cuda_bf16.h>
#include <cuda_fp16.h>
#include <cstdint>

#define NN 20000
#define NE 400000
#define H  256

// ------- static scratch (allocations forbidden) -------
__device__ unsigned short g_a16[2][NN*H]; // f16 src-side preact
__device__ unsigned short g_c16[2][NN*H]; // f16 dst-side preact
__device__ unsigned g_segout[2][NN*H];   // mapped-uint running max, 0 = empty
__device__ float    g_xw[2][NN*128];
__device__ float    g_h2[NN*256];
__device__ int      g_deg[2][NN];
__device__ int      g_offs[2][NN+1];
__device__ int      g_cursor[2][NN];
__device__ int      g_ssrc[2][NE];
__device__ int      g_sdst[2][NE];
__device__ float    g_dinv[2][NN];
__device__ float    g_partial[1024*3];
__device__ unsigned short g_w2h[2][H*H];  // f16 hi of W2^T, [chunk][n][64k]
__device__ unsigned char  g_w2l8[2][H*H]; // e5m2 of (residual * 2^10)
__device__ unsigned short g_gwh[2][512*128]; // bf16 hi of gW^T
__device__ unsigned short g_gwl[2][512*128];

__device__ __forceinline__ unsigned fmap(float f) {
    unsigned b = __float_as_uint(f);
    return b ^ ((unsigned)((int)b >> 31) | 0x80000000u);
}
__device__ __forceinline__ uint32_t smem_u32(const void* p) {
    uint32_t a;
    asm("{ .reg .u64 t; cvta.to.shared.u64 t, %1; cvt.u32.u64 %0, t; }" : "=r"(a) : "l"(p));
    return a;
}
__device__ __forceinline__ void mma_bf16(float* c, const uint32_t* a,
                                         uint32_t b0, uint32_t b1) {
    asm("mma.sync.aligned.m16n8k16.row.col.f32.bf16.bf16.f32 "
        "{%0,%1,%2,%3}, {%4,%5,%6,%7}, {%8,%9}, {%0,%1,%2,%3};"
        : "+f"(c[0]), "+f"(c[1]), "+f"(c[2]), "+f"(c[3])
        : "r"(a[0]), "r"(a[1]), "r"(a[2]), "r"(a[3]), "r"(b0), "r"(b1));
}
__device__ __forceinline__ void mma_f16f32(float* c, const uint32_t* a,
                                           uint32_t b0, uint32_t b1) {
    asm("mma.sync.aligned.m16n8k16.row.col.f32.f16.f16.f32 "
        "{%0,%1,%2,%3}, {%4,%5,%6,%7}, {%8,%9}, {%0,%1,%2,%3};"
        : "+f"(c[0]), "+f"(c[1]), "+f"(c[2]), "+f"(c[3])
        : "r"(a[0]), "r"(a[1]), "r"(a[2]), "r"(a[3]), "r"(b0), "r"(b1));
}
__device__ __forceinline__ void ldsm4(uint32_t* r, uint32_t addr) {
    asm volatile("ldmatrix.sync.aligned.m8n8.x4.shared.b16 {%0,%1,%2,%3}, [%4];"
        : "=r"(r[0]), "=r"(r[1]), "=r"(r[2]), "=r"(r[3]) : "r"(addr));
}
__device__ __forceinline__ void bf16split(float h, float h1, uint32_t& hi, uint32_t& lo) {
    asm("cvt.rn.bf16x2.f32 %0, %1, %2;" : "=r"(hi) : "f"(h1), "f"(h));
    float r0 = h - __uint_as_float(hi << 16);
    float r1 = h1 - __uint_as_float(hi & 0xffff0000u);
    asm("cvt.rn.bf16x2.f32 %0, %1, %2;" : "=r"(lo) : "f"(r1), "f"(r0));
}
__device__ __forceinline__ uint32_t prmt0(uint32_t a, uint32_t sel) {
    uint32_t d;
    asm("prmt.b32 %0, %1, 0, %2;" : "=r"(d) : "r"(a), "r"(sel));
    return d;
}
__device__ __forceinline__ uint32_t hmul2c(uint32_t a) { // f16x2 * 2^-10
    uint32_t d;
    asm("mul.f16x2 %0, %1, %2;" : "=r"(d) : "r"(a), "r"(0x14001400u));
    return d;
}
__device__ __forceinline__ uint32_t hsubrelu2(uint32_t a, uint32_t b) {
    uint32_t d;
    asm("sub.f16x2 %0, %1, %2;" : "=r"(d) : "r"(a), "r"(b));
    asm("max.f16x2 %0, %1, %2;" : "=r"(d) : "r"(d), "r"(0u));
    return d;
}

// ------- fused prep kernels -------
// uv: clears segout, computes f16 a/c, and accumulates degrees (deg pre-cleared by w2prep)
__global__ void uv_fused(const float* __restrict__ pos0, const float* __restrict__ pos1,
                         const float* __restrict__ W10, const float* __restrict__ W11,
                         const float* __restrict__ b10, const float* __restrict__ b11,
                         const int* __restrict__ ei0, const int* __restrict__ ei1) {
    int gid = blockIdx.x*256 + threadIdx.x;
    (&g_segout[0][0])[gid] = 0u;
    if (gid < 2*NE) {
        int ge = gid / NE, e = gid - ge*NE;
        const int* ei = ge ? ei1 : ei0;
        atomicAdd(&g_deg[ge][ei[NE + e]], 1);
    }
    int g = blockIdx.x / NN, i = blockIdx.x - g*NN, ch = threadIdx.x;
    const float* pos = g ? pos1 : pos0;
    const float* W1  = g ? W11 : W10;
    const float* bb  = g ? b11 : b10;
    float p0 = pos[i*3+0], p1 = pos[i*3+1], p2 = pos[i*3+2];
    float c = p0*W1[3*H+ch] + p1*W1[4*H+ch] + p2*W1[5*H+ch];
    float a = p0*W1[0*H+ch] + p1*W1[1*H+ch] + p2*W1[2*H+ch] + c + bb[ch];
    __half ah = __float2half_rn(a), chh = __float2half_rn(c);
    g_a16[g][i*H+ch] = *(unsigned short*)&ah;
    g_c16[g][i*H+ch] = *(unsigned short*)&chh;
}

// W2: f16 hi + e5m2 lo, transposed [chunk][n][64k]; also clears deg
__global__ void w2prep_fused(const float* __restrict__ W20, const float* __restrict__ W21) {
    int gid = blockIdx.x * 256 + threadIdx.x;
    if (gid < 2*NN) (&g_deg[0][0])[gid] = 0;
    int g = blockIdx.x >> 8;
    int idx = (blockIdx.x & 255) * 256 + threadIdx.x;
    int k = idx >> 8, n = idx & 255;
    float w = (g ? W21 : W20)[idx];
    __half hb = __float2half_rn(w);
    float r = (w - __half2float(hb)) * 1024.f;
    __half rb = __float2half_rn(r);
    unsigned short rbits = *(unsigned short*)&rb;
    unsigned char lo8 = (unsigned char)(((unsigned)rbits + 0x7Fu + ((rbits >> 8) & 1u)) >> 8);
    int o = (k >> 6)*16384 + n*64 + (k & 63);
    g_w2h[g][o]  = *(unsigned short*)&hb;
    g_w2l8[g][o] = lo8;
}

__global__ void gwprep_fused(const float* __restrict__ Wg0, const float* __restrict__ Wg1) {
    int g = blockIdx.x >> 8;
    int idx = (blockIdx.x & 255) * 256 + threadIdx.x;
    int k = idx >> 7, n = idx & 127;
    float w = (g ? Wg1 : Wg0)[idx];
    __nv_bfloat16 hb = __float2bfloat16(w);
    float hf = __bfloat162float(hb);
    __nv_bfloat16 lb = __float2bfloat16(w - hf);
    int o = (k >> 6)*8192 + n*64 + (k & 63);
    g_gwh[g][o] = *(unsigned short*)&hb;
    g_gwl[g][o] = *(unsigned short*)&lb;
}

__global__ void scan_fused() {
    __shared__ int ss[1024];
    int g = blockIdx.x;
    int t = threadIdx.x;
    const int CH = (NN + 1023) / 1024;
    int beg = t * CH, end = beg + CH;
    if (end > NN) end = NN;
    if (beg > NN) beg = NN;
    int s = 0;
    for (int i = beg; i < end; i++) s += g_deg[g][i];
    ss[t] = s;
    __syncthreads();
    for (int off = 1; off < 1024; off <<= 1) {
        int v = (t >= off) ? ss[t-off] : 0;
        __syncthreads();
        ss[t] += v;
        __syncthreads();
    }
    int run = (t == 0) ? 0 : ss[t-1];
    for (int i = beg; i < end; i++) {
        int d = g_deg[g][i];
        g_offs[g][i] = run; g_cursor[g][i] = run; run += d;
        g_dinv[g][i] = rsqrtf(1.f + (float)d);
    }
    if (t == 1023) g_offs[g][NN] = NE;
}

__global__ void fill_fused(const int* __restrict__ ei0, const int* __restrict__ ei1) {
    int idx = blockIdx.x * 256 + threadIdx.x;
    if (idx < 2*NE) {
        int g = idx / NE, e = idx - g*NE;
        const int* ei = g ? ei1 : ei0;
        int d = ei[NE + e];
        int p = atomicAdd(&g_cursor[g][d], 1);
        g_ssrc[g][p] = ei[e];
        g_sdst[g][p] = d;
    }
}

// ------- pointnet: 64 edges x 256 ch per CTA, f16 2-product, f16 gather -------
#define OFF_AH 0
#define OFF_WH 9216
#define OFF_WL 46080
#define OFF_DST 82944
#define PN_SMEM 83456
#define TILES_PER_G 6250

__global__ __launch_bounds__(256, 2)
void pointnet_mma(const float* __restrict__ b20, const float* __restrict__ b21) {
    extern __shared__ char AB[];
    uint32_t abu = smem_u32(AB);
    int tid = threadIdx.x, lane = tid & 31, wid = tid >> 5;
    int g = (blockIdx.x >= TILES_PER_G) ? 1 : 0;
    int e0 = (blockIdx.x - g*TILES_PER_G) * 64;
    const float* __restrict__ b2 = g ? b21 : b20;
    int* s_dst = (int*)(AB + OFF_DST);
    if (tid < 64) s_dst[tid] = g_sdst[g][e0 + tid];

    int ge = tid >> 2, kq = (tid & 3) * 16;
    int esrc = g_ssrc[g][e0 + ge] * 256;
    int edst = g_sdst[g][e0 + ge] * 256;
    const unsigned short* __restrict__ Aa = g_a16[g];
    const unsigned short* __restrict__ Cc = g_c16[g];

    int eg = wid >> 2, cg = wid & 3;
    int qrow = lane >> 2;
    int qc = (lane & 3) * 2;

    uint32_t aH = abu + OFF_AH + (uint32_t)(eg*32 + (lane & 15))*144 + (lane >> 4)*16;
    uint32_t bH = abu + OFF_WH +
        (uint32_t)(cg*64 + (lane >> 4)*8 + (lane & 7))*144 + ((lane >> 3) & 1)*16;
    uint32_t bL = bH + (OFF_WL - OFF_WH);

    float acc[2][8][4];
#pragma unroll
    for (int mt = 0; mt < 2; mt++)
#pragma unroll
        for (int nt = 0; nt < 8; nt++)
#pragma unroll
            for (int j = 0; j < 4; j++) acc[mt][nt][j] = 0.f;

    for (int ck = 0; ck < 4; ck++) {
        // ---- gather f16 a/c, h = relu(a-c) in f16x2 ----
        {
            int k0 = ck*64 + kq;
            const uint4* pa = (const uint4*)(Aa + esrc + k0);
            const uint4* pc = (const uint4*)(Cc + edst + k0);
            uint4 a0 = pa[0], a1 = pa[1];
            uint4 c0 = pc[0], c1 = pc[1];
            uint4 o0, o1;
            o0.x = hsubrelu2(a0.x, c0.x); o0.y = hsubrelu2(a0.y, c0.y);
            o0.z = hsubrelu2(a0.z, c0.z); o0.w = hsubrelu2(a0.w, c0.w);
            o1.x = hsubrelu2(a1.x, c1.x); o1.y = hsubrelu2(a1.y, c1.y);
            o1.z = hsubrelu2(a1.z, c1.z); o1.w = hsubrelu2(a1.w, c1.w);
            char* ph = AB + OFF_AH + (tid >> 2)*144 + kq*2;
            *(uint4*)ph        = o0;
            *(uint4*)(ph + 16) = o1;
        }
        // ---- stream W chunk: hi f16 direct, lo e5m2 expand ----
        {
            const uint4* gh4 = (const uint4*)(g_w2h[g] + ck*16384);
#pragma unroll
            for (int i = 0; i < 8; i++) {
                int idx = tid + i*256;
                int row = idx >> 3, q = idx & 7;
                *(uint4*)(AB + OFF_WH + row*144 + q*16) = gh4[idx];
            }
            const uint4* gl8 = (const uint4*)(g_w2l8[g] + ck*16384);
#pragma unroll
            for (int i = 0; i < 4; i++) {
                int row = (tid >> 2) + i*64, part = tid & 3;
                uint4 s4 = gl8[row*4 + part];
                uint32_t s[4] = {s4.x, s4.y, s4.z, s4.w};
                uint32_t o[8];
#pragma unroll
                for (int j = 0; j < 4; j++) {
                    o[2*j]   = hmul2c(prmt0(s[j], 0x1404u));
                    o[2*j+1] = hmul2c(prmt0(s[j], 0x3424u));
                }
                char* dst = AB + OFF_WL + row*144 + part*32;
                *(uint4*)dst        = make_uint4(o[0], o[1], o[2], o[3]);
                *(uint4*)(dst + 16) = make_uint4(o[4], o[5], o[6], o[7]);
            }
        }
        __syncthreads();

        // ---- MMA: 2 f16 products ----
#pragma unroll
        for (int kk = 0; kk < 4; kk++) {
            uint32_t ko = kk*32;
            uint32_t bh[4][4], bl[4][4];
#pragma unroll
            for (int p = 0; p < 4; p++) {
                ldsm4(bh[p], bH + p*(16*144) + ko);
                ldsm4(bl[p], bL + p*(16*144) + ko);
            }
#pragma unroll
            for (int mt = 0; mt < 2; mt++) {
                uint32_t ah[4];
                ldsm4(ah, aH + mt*(16*144) + ko);
#pragma unroll
                for (int p = 0; p < 4; p++) {
                    mma_f16f32(acc[mt][2*p],   ah, bh[p][0], bh[p][1]);
                    mma_f16f32(acc[mt][2*p+1], ah, bh[p][2], bh[p][3]);
                    mma_f16f32(acc[mt][2*p],   ah, bl[p][0], bl[p][1]);
                    mma_f16f32(acc[mt][2*p+1], ah, bl[p][2], bl[p][3]);
                }
            }
        }
        __syncthreads();
    }

    float* buf = (float*)AB;
#pragma unroll
    for (int mt = 0; mt < 2; mt++) {
        int row = eg*32 + mt*16 + qrow;
#pragma unroll
        for (int nt = 0; nt < 8; nt++) {
            int col = cg*64 + nt*8 + qc;
            buf[row*257 + col]       = acc[mt][nt][0];
            buf[row*257 + col + 1]   = acc[mt][nt][1];
            buf[(row+8)*257 + col]   = acc[mt][nt][2];
            buf[(row+8)*257 + col+1] = acc[mt][nt][3];
        }
    }
    __syncthreads();
    {
        unsigned* __restrict__ seg = &g_segout[g][0];
        int gch = tid;
        float bias = b2[gch];
        int cur = s_dst[0];
        float mx = buf[gch];
        for (int q = 1; q < 64; q++) {
            int d = s_dst[q];
            float v = buf[q*257 + gch];
            if (d != cur) {
                atomicMax(&seg[cur*256 + gch], fmap(mx + bias));
                cur = d; mx = v;
            } else mx = fmaxf(mx, v);
        }
        atomicMax(&seg[cur*256 + gch], fmap(mx + bias));
    }
}

// ------- xw via HMMA: [NN,512]@[512,128] per graph, 3-term bf16 -------
#define XOFF_AH 0
#define XOFF_AL 18432
#define XOFF_WH 36864
#define XOFF_WL 55296
#define XW_SMEM 73728
#define XW_TILES 157

__global__ __launch_bounds__(256, 2)
void xw_mma() {
    extern __shared__ char AB[];
    uint32_t abu = smem_u32(AB);
    int tid = threadIdx.x, lane = tid & 31, wid = tid >> 5;
    int g = (blockIdx.x >= XW_TILES) ? 1 : 0;
    int row0 = (blockIdx.x - g*XW_TILES) * 128;

    int grow = tid >> 1, kh = (tid & 1) * 32;
    int ar = row0 + grow; if (ar > NN-1) ar = NN-1;

    int eg = wid >> 1, cg = wid & 1;
    int qrow = lane >> 2;
    int qc = (lane & 3) * 2;

    uint32_t aH = abu + XOFF_AH + (uint32_t)(eg*32 + (lane & 15))*144 + (lane >> 4)*16;
    uint32_t aL = aH + (XOFF_AL - XOFF_AH);
    uint32_t bH = abu + XOFF_WH +
        (uint32_t)(cg*64 + (lane >> 4)*8 + (lane & 7))*144 + ((lane >> 3) & 1)*16;
    uint32_t bL = bH + (XOFF_WL - XOFF_WH);

    float acc[2][8][4];
#pragma unroll
    for (int mt = 0; mt < 2; mt++)
#pragma unroll
        for (int nt = 0; nt < 8; nt++)
#pragma unroll
            for (int j = 0; j < 4; j++) acc[mt][nt][j] = 0.f;

    for (int ck = 0; ck < 8; ck++) {
        {
            int kbase = ck*64 + kh;
            const unsigned* sp = (kbase < 256) ? &g_segout[0][ar*256 + kbase]
                                               : &g_segout[1][ar*256 + kbase - 256];
            char* ph = AB + XOFF_AH + grow*144 + kh*2;
            char* pl = AB + XOFF_AL + grow*144 + kh*2;
#pragma unroll
            for (int q = 0; q < 8; q++) {
                uint4 u = *(const uint4*)(sp + q*4);
                float h0 = (u.x > 0x80000000u) ? __uint_as_float(u.x ^ 0x80000000u) : 0.f;
                float h1 = (u.y > 0x80000000u) ? __uint_as_float(u.y ^ 0x80000000u) : 0.f;
                float h2 = (u.z > 0x80000000u) ? __uint_as_float(u.z ^ 0x80000000u) : 0.f;
                float h3 = (u.w > 0x80000000u) ? __uint_as_float(u.w ^ 0x80000000u) : 0.f;
                uint32_t hi0, hi1, lo0, lo1;
                bf16split(h0, h1, hi0, lo0);
                bf16split(h2, h3, hi1, lo1);
                *(uint32_t*)(ph + q*8)     = hi0;
                *(uint32_t*)(ph + q*8 + 4) = hi1;
                *(uint32_t*)(pl + q*8)     = lo0;
                *(uint32_t*)(pl + q*8 + 4) = lo1;
            }
        }
        {
            const uint4* gh4 = (const uint4*)(g_gwh[g] + ck*8192);
            const uint4* gl4 = (const uint4*)(g_gwl[g] + ck*8192);
#pragma unroll
            for (int i = 0; i < 4; i++) {
                int idx = tid + i*256;
                int row = idx >> 3, q = idx & 7;
                *(uint4*)(AB + XOFF_WH + row*144 + q*16) = gh4[idx];
                *(uint4*)(AB + XOFF_WL + row*144 + q*16) = gl4[idx];
            }
        }
        __syncthreads();

#pragma unroll
        for (int kk = 0; kk < 4; kk++) {
            uint32_t ko = kk*32;
            uint32_t bh[4][4], bl[4][4];
#pragma unroll
            for (int p = 0; p < 4; p++) {
                ldsm4(bh[p], bH + p*(16*144) + ko);
                ldsm4(bl[p], bL + p*(16*144) + ko);
            }
#pragma unroll
            for (int mt = 0; mt < 2; mt++) {
                uint32_t ah[4];
                ldsm4(ah, aH + mt*(16*144) + ko);
#pragma unroll
                for (int p = 0; p < 4; p++) {
                    mma_bf16(acc[mt][2*p],   ah, bh[p][0], bh[p][1]);
                    mma_bf16(acc[mt][2*p+1], ah, bh[p][2], bh[p][3]);
                }
            }
#pragma unroll
            for (int mt = 0; mt < 2; mt++) {
                uint32_t al[4];
                ldsm4(al, aL + mt*(16*144) + ko);
#pragma unroll
                for (int p = 0; p < 4; p++) {
                    mma_bf16(acc[mt][2*p],   al, bh[p][0], bh[p][1]);
                    mma_bf16(acc[mt][2*p+1], al, bh[p][2], bh[p][3]);
                }
            }
#pragma unroll
            for (int mt = 0; mt < 2; mt++) {
                uint32_t ah2[4];
                ldsm4(ah2, aH + mt*(16*144) + ko);
#pragma unroll
                for (int p = 0; p < 4; p++) {
                    mma_bf16(acc[mt][2*p],   ah2, bl[p][0], bl[p][1]);
                    mma_bf16(acc[mt][2*p+1], ah2, bl[p][2], bl[p][3]);
                }
            }
        }
        __syncthreads();
    }

    float* __restrict__ xw = g_xw[g];
#pragma unroll
    for (int mt = 0; mt < 2; mt++) {
        int r0 = row0 + eg*32 + mt*16 + qrow;
#pragma unroll
        for (int nt = 0; nt < 8; nt++) {
            int col = cg*64 + nt*8 + qc;
            if (r0 < NN)
                *(float2*)(xw + r0*128 + col) = make_float2(acc[mt][nt][0], acc[mt][nt][1]);
            if (r0 + 8 < NN)
                *(float2*)(xw + (r0+8)*128 + col) = make_float2(acc[mt][nt][2], acc[mt][nt][3]);
        }
    }
}

// ------- agg: one block per node, both graphs, float2 channels -------
__global__ void agg_paired(const float* __restrict__ gb0, const float* __restrict__ gb1) {
    int i = blockIdx.x;
    int t = threadIdx.x;
    int g = t >> 6;
    int ch = (t & 63) * 2;
    const float* __restrict__ xw = g_xw[g];
    const float* __restrict__ bias = g ? gb1 : gb0;
    float di = g_dinv[g][i];
    int beg = g_offs[g][i], end = g_offs[g][i+1];
    float ax = 0.f, ay = 0.f;
    for (int e = beg; e < end; e++) {
        int s = g_ssrc[g][e];
        float2 v = *(const float2*)(xw + s*128 + ch);
        float dv = g_dinv[g][s];
        ax += v.x * dv; ay += v.y * dv;
    }
    float2 self = *(const float2*)(xw + i*128 + ch);
    float d2 = di*di;
    float vx = di*ax + self.x*d2 + bias[ch];
    float vy = di*ay + self.y*d2 + bias[ch+1];
    *(float2*)(&g_h2[i*256 + g*128 + ch]) = make_float2(fmaxf(vx, 0.f), fmaxf(vy, 0.f));
}

__global__ __launch_bounds__(256)
void c3cls_kernel(const float* __restrict__ Wc, const float* __restrict__ bc,
                  const float* __restrict__ clsW) {
    __shared__ float s_a[64*16];
    __shared__ float4 s_b[16*32];
    __shared__ float red[256];
    int tid = threadIdx.x, tx = tid & 31, ty = tid >> 5;
    int row0 = blockIdx.x * 64;
    float acc[8][4];
#pragma unroll
    for (int i = 0; i < 8; i++)
#pragma unroll
        for (int j = 0; j < 4; j++) acc[i][j] = 0.f;
    int lr = tid >> 2, lk = (tid & 3) * 4;
    int ar = row0 + lr; if (ar > NN-1) ar = NN-1;
    const float4* B4 = (const float4*)Wc;
    for (int k0 = 0; k0 < 256; k0 += 16) {
        float4 av = *(const float4*)(g_h2 + ar*256 + k0 + lk);
        float4 bv[2];
#pragma unroll
        for (int q = 0; q < 2; q++) {
            int idx = tid + q*256;
            bv[q] = B4[(k0 + (idx >> 5))*32 + (idx & 31)];
        }
        __syncthreads();
        *(float4*)(s_a + lr*16 + lk) = av;
#pragma unroll
        for (int q = 0; q < 2; q++) s_b[tid + q*256] = bv[q];
        __syncthreads();
#pragma unroll
        for (int kk = 0; kk < 16; kk++) {
            float4 b = s_b[kk*32 + tx];
#pragma unroll
            for (int i = 0; i < 8; i++) {
                float a = s_a[(ty*8 + i)*16 + kk];
                acc[i][0] += a*b.x; acc[i][1] += a*b.y;
                acc[i][2] += a*b.z; acc[i][3] += a*b.w;
            }
        }
    }
    float sum0 = 0.f, sum1 = 0.f, sum2 = 0.f;
#pragma unroll
    for (int i = 0; i < 8; i++) {
        int r = row0 + ty*8 + i;
        if (r < NN) {
#pragma unroll
            for (int jj = 0; jj < 4; jj++) {
                float v = fmaxf(acc[i][jj] + bc[tx*4 + jj], 0.f);
                const float* w = clsW + (r*128 + tx*4 + jj)*3;
                sum0 += v*w[0]; sum1 += v*w[1]; sum2 += v*w[2];
            }
        }
    }
    float sums[3] = {sum0, sum1, sum2};
#pragma unroll
    for (int r3 = 0; r3 < 3; r3++) {
        red[tid] = sums[r3];
        __syncthreads();
        for (int s = 128; s > 0; s >>= 1) {
            if (tid < s) red[tid] += red[tid + s];
            __syncthreads();
        }
        if (tid == 0) g_partial[blockIdx.x*3 + r3] = red[0];
        __syncthreads();
    }
}

__global__ void final_kernel(const float* __restrict__ clsb, float* __restrict__ out, int nblk) {
    int r = threadIdx.x;
    if (r < 3) {
        double s = (double)clsb[r];
        for (int i = 0; i < nblk; i++) s += (double)g_partial[i*3 + r];
        out[r] = (float)s;
    }
}

extern "C" void kernel_launch(void* const* d_in, const int* in_sizes, int n_in,
                              void* d_out, int out_size) {
    const float *pos[2]={0,0}, *W1[2]={0,0}, *b1[2]={0,0}, *W2[2]={0,0}, *b2[2]={0,0};
    const float *gW[2]={0,0}, *gb[2]={0,0}, *cW=0, *cb=0, *clsW=0, *clsb=0;
    const int *ei[2]={0,0};
    int npos=0, nei=0, nw1=0, n256=0, n64k=0, n128=0;
    for (int i = 0; i < n_in; i++) {
        int sz = in_sizes[i];
        const float* f = (const float*)d_in[i];
        if (sz == 3*NN)            { if (npos<2) pos[npos++] = f; }
        else if (sz == 2*NE)       { if (nei<2)  ei[nei++] = (const int*)d_in[i]; }
        else if (sz == 6*H)        { if (nw1<2)  W1[nw1++] = f; }
        else if (sz == H)          { int j=n256++; if(j==0)b1[0]=f; else if(j==1)b2[0]=f;
                                     else if(j==2)b1[1]=f; else if(j==3)b2[1]=f; }
        else if (sz == H*H)        { int j=n64k++; if(j<2) W2[j]=f; else if(j<4) gW[j-2]=f; }
        else if (sz == H/2)        { int j=n128++; if(j<2) gb[j]=f; else cb=f; }
        else if (sz == H*(H/2))    { cW = f; }
        else if (sz == NN*(H/2)*3) { clsW = f; }
        else if (sz == 3)          { clsb = f; }
    }

    static bool attr_done = false;
    if (!attr_done) {
        cudaFuncSetAttribute(pointnet_mma, cudaFuncAttributeMaxDynamicSharedMemorySize, PN_SMEM);
        cudaFuncSetAttribute(xw_mma, cudaFuncAttributeMaxDynamicSharedMemorySize, XW_SMEM);
        attr_done = true;
    }

    w2prep_fused<<<512, 256>>>(W2[0], W2[1]);          // clears deg
    gwprep_fused<<<512, 256>>>(gW[0], gW[1]);
    uv_fused<<<2*NN, 256>>>(pos[0], pos[1], W1[0], W1[1], b1[0], b1[1], ei[0], ei[1]); // + deg atomics
    scan_fused<<<2, 1024>>>();
    fill_fused<<<(2*NE + 255)/256, 256>>>(ei[0], ei[1]);
    pointnet_mma<<<2*TILES_PER_G, 256, PN_SMEM>>>(b2[0], b2[1]);
    xw_mma<<<2*XW_TILES, 256, XW_SMEM>>>();
    agg_paired<<<NN, 128>>>(gb[0], gb[1]);
    int nblk = (NN + 63)/64;
    c3cls_kernel<<<nblk, 256>>>(cW, cb, clsW);
    final_kernel<<<1, 32>>>(clsb, (float*)d_out, nblk);
}

// round 17
// speedup vs baseline: 3.5542x; 1.0854x over previous
#include <cuda_runtime.h>
#include <cuda_bf16.h>
#include <cuda_fp16.h>
#include <cstdint>

#define NN 20000
#define NE 400000
#define H  256

// ------- static scratch (allocations forbidden) -------
__device__ unsigned short g_a16[2][NN*H]; // f16 src-side preact
__device__ unsigned short g_c16[2][NN*H]; // f16 dst-side preact
__device__ unsigned g_segout[2][NN*H];   // mapped-uint running max, 0 = empty
__device__ float    g_xw[2][NN*128];
__device__ float    g_h2[NN*256];
__device__ int      g_deg[2][NN];
__device__ int      g_offs[2][NN+1];
__device__ int      g_cursor[2][NN];
__device__ int      g_spart[160];
__device__ int      g_ssrc[2][NE];
__device__ int      g_sdst[2][NE];
__device__ float    g_dinv[2][NN];
__device__ float    g_partial[1024*3];
__device__ unsigned short g_w2h[2][H*H];  // f16 hi of W2^T, [chunk][n][64k]
__device__ unsigned char  g_w2l8[2][H*H]; // e5m2 of (residual * 2^10)
__device__ unsigned short g_gwh[2][512*128]; // bf16 hi of gW^T
__device__ unsigned short g_gwl[2][512*128];

__device__ __forceinline__ unsigned fmap(float f) {
    unsigned b = __float_as_uint(f);
    return b ^ ((unsigned)((int)b >> 31) | 0x80000000u);
}
__device__ __forceinline__ uint32_t smem_u32(const void* p) {
    uint32_t a;
    asm("{ .reg .u64 t; cvta.to.shared.u64 t, %1; cvt.u32.u64 %0, t; }" : "=r"(a) : "l"(p));
    return a;
}
__device__ __forceinline__ void mma_bf16(float* c, const uint32_t* a,
                                         uint32_t b0, uint32_t b1) {
    asm("mma.sync.aligned.m16n8k16.row.col.f32.bf16.bf16.f32 "
        "{%0,%1,%2,%3}, {%4,%5,%6,%7}, {%8,%9}, {%0,%1,%2,%3};"
        : "+f"(c[0]), "+f"(c[1]), "+f"(c[2]), "+f"(c[3])
        : "r"(a[0]), "r"(a[1]), "r"(a[2]), "r"(a[3]), "r"(b0), "r"(b1));
}
__device__ __forceinline__ void mma_f16f32(float* c, const uint32_t* a,
                                           uint32_t b0, uint32_t b1) {
    asm("mma.sync.aligned.m16n8k16.row.col.f32.f16.f16.f32 "
        "{%0,%1,%2,%3}, {%4,%5,%6,%7}, {%8,%9}, {%0,%1,%2,%3};"
        : "+f"(c[0]), "+f"(c[1]), "+f"(c[2]), "+f"(c[3])
        : "r"(a[0]), "r"(a[1]), "r"(a[2]), "r"(a[3]), "r"(b0), "r"(b1));
}
__device__ __forceinline__ void ldsm4(uint32_t* r, uint32_t addr) {
    asm volatile("ldmatrix.sync.aligned.m8n8.x4.shared.b16 {%0,%1,%2,%3}, [%4];"
        : "=r"(r[0]), "=r"(r[1]), "=r"(r[2]), "=r"(r[3]) : "r"(addr));
}
__device__ __forceinline__ void bf16split(float h, float h1, uint32_t& hi, uint32_t& lo) {
    asm("cvt.rn.bf16x2.f32 %0, %1, %2;" : "=r"(hi) : "f"(h1), "f"(h));
    float r0 = h - __uint_as_float(hi << 16);
    float r1 = h1 - __uint_as_float(hi & 0xffff0000u);
    asm("cvt.rn.bf16x2.f32 %0, %1, %2;" : "=r"(lo) : "f"(r1), "f"(r0));
}
__device__ __forceinline__ uint32_t prmt0(uint32_t a, uint32_t sel) {
    uint32_t d;
    asm("prmt.b32 %0, %1, 0, %2;" : "=r"(d) : "r"(a), "r"(sel));
    return d;
}
__device__ __forceinline__ uint32_t hmul2c(uint32_t a) { // f16x2 * 2^-10
    uint32_t d;
    asm("mul.f16x2 %0, %1, %2;" : "=r"(d) : "r"(a), "r"(0x14001400u));
    return d;
}
__device__ __forceinline__ uint32_t hsubrelu2(uint32_t a, uint32_t b) {
    uint32_t d;
    asm("sub.f16x2 %0, %1, %2;" : "=r"(d) : "r"(a), "r"(b));
    asm("max.f16x2 %0, %1, %2;" : "=r"(d) : "r"(d), "r"(0u));
    return d;
}
__device__ __forceinline__ void cpasync16(uint32_t smem, const void* g) {
    asm volatile("cp.async.cg.shared.global [%0], [%1], 16;" :: "r"(smem), "l"(g));
}
#define CP_COMMIT() asm volatile("cp.async.commit_group;" ::: "memory")
#define CP_WAIT0()  asm volatile("cp.async.wait_group 0;" ::: "memory")

// ------- fused prep kernels -------
__global__ void uv_fused(const float* __restrict__ pos0, const float* __restrict__ pos1,
                         const float* __restrict__ W10, const float* __restrict__ W11,
                         const float* __restrict__ b10, const float* __restrict__ b11,
                         const int* __restrict__ ei0, const int* __restrict__ ei1) {
    int gid = blockIdx.x*256 + threadIdx.x;
    (&g_segout[0][0])[gid] = 0u;
    if (gid < 2*NE) {
        int ge = gid / NE, e = gid - ge*NE;
        const int* ei = ge ? ei1 : ei0;
        atomicAdd(&g_deg[ge][ei[NE + e]], 1);
    }
    int g = blockIdx.x / NN, i = blockIdx.x - g*NN, ch = threadIdx.x;
    const float* pos = g ? pos1 : pos0;
    const float* W1  = g ? W11 : W10;
    const float* bb  = g ? b11 : b10;
    float p0 = pos[i*3+0], p1 = pos[i*3+1], p2 = pos[i*3+2];
    float c = p0*W1[3*H+ch] + p1*W1[4*H+ch] + p2*W1[5*H+ch];
    float a = p0*W1[0*H+ch] + p1*W1[1*H+ch] + p2*W1[2*H+ch] + c + bb[ch];
    __half ah = __float2half_rn(a), chh = __float2half_rn(c);
    g_a16[g][i*H+ch] = *(unsigned short*)&ah;
    g_c16[g][i*H+ch] = *(unsigned short*)&chh;
}

__global__ void w2prep_fused(const float* __restrict__ W20, const float* __restrict__ W21) {
    int gid = blockIdx.x * 256 + threadIdx.x;
    if (gid < 2*NN) (&g_deg[0][0])[gid] = 0;
    int g = blockIdx.x >> 8;
    int idx = (blockIdx.x & 255) * 256 + threadIdx.x;
    int k = idx >> 8, n = idx & 255;
    float w = (g ? W21 : W20)[idx];
    __half hb = __float2half_rn(w);
    float r = (w - __half2float(hb)) * 1024.f;
    __half rb = __float2half_rn(r);
    unsigned short rbits = *(unsigned short*)&rb;
    unsigned char lo8 = (unsigned char)(((unsigned)rbits + 0x7Fu + ((rbits >> 8) & 1u)) >> 8);
    int o = (k >> 6)*16384 + n*64 + (k & 63);
    g_w2h[g][o]  = *(unsigned short*)&hb;
    g_w2l8[g][o] = lo8;
}

__global__ void gwprep_fused(const float* __restrict__ Wg0, const float* __restrict__ Wg1) {
    int g = blockIdx.x >> 8;
    int idx = (blockIdx.x & 255) * 256 + threadIdx.x;
    int k = idx >> 7, n = idx & 127;
    float w = (g ? Wg1 : Wg0)[idx];
    __nv_bfloat16 hb = __float2bfloat16(w);
    float hf = __bfloat162float(hb);
    __nv_bfloat16 lb = __float2bfloat16(w - hf);
    int o = (k >> 6)*8192 + n*64 + (k & 63);
    g_gwh[g][o] = *(unsigned short*)&hb;
    g_gwl[g][o] = *(unsigned short*)&lb;
}

// ------- 3-phase CSR scan (replaces 2-block scan_fused) -------
// 80 blocks per graph x 250 nodes per block
__global__ void scan_a() {
    int g = blockIdx.x / 80, blk = blockIdx.x - g*80;
    int t = threadIdx.x;
    __shared__ int sh[256];
    int v = (t < 250) ? g_deg[g][blk*250 + t] : 0;
    sh[t] = v;
    __syncthreads();
    for (int s = 128; s > 0; s >>= 1) {
        if (t < s) sh[t] += sh[t + s];
        __syncthreads();
    }
    if (t == 0) g_spart[blockIdx.x] = sh[0];
}
__global__ void scan_b() {
    int t = threadIdx.x;
    __shared__ int sh[160];
    if (t < 160) sh[t] = g_spart[t];
    __syncthreads();
    if (t == 0) {
        int run = 0;
        for (int i = 0; i < 80; i++)  { int v = sh[i]; sh[i] = run; run += v; }
        run = 0;
        for (int i = 80; i < 160; i++){ int v = sh[i]; sh[i] = run; run += v; }
    }
    __syncthreads();
    if (t < 160) g_spart[t] = sh[t];
}
__global__ void scan_c() {
    int g = blockIdx.x / 80, blk = blockIdx.x - g*80;
    int t = threadIdx.x;
    __shared__ int sh[256];
    int d = (t < 250) ? g_deg[g][blk*250 + t] : 0;
    sh[t] = d;
    __syncthreads();
    for (int off = 1; off < 256; off <<= 1) {
        int v = (t >= off) ? sh[t-off] : 0;
        __syncthreads();
        sh[t] += v;
        __syncthreads();
    }
    if (t < 250) {
        int i = blk*250 + t;
        int excl = sh[t] - d + g_spart[blockIdx.x];
        g_offs[g][i] = excl;
        g_cursor[g][i] = excl;
        g_dinv[g][i] = rsqrtf(1.f + (float)d);
    }
    if (blk == 79 && t == 0) g_offs[g][NN] = NE;
}

__global__ void fill_fused(const int* __restrict__ ei0, const int* __restrict__ ei1) {
    int idx = blockIdx.x * 256 + threadIdx.x;
    if (idx < 2*NE) {
        int g = idx / NE, e = idx - g*NE;
        const int* ei = g ? ei1 : ei0;
        int d = ei[NE + e];
        int p = atomicAdd(&g_cursor[g][d], 1);
        g_ssrc[g][p] = ei[e];
        g_sdst[g][p] = d;
    }
}

// ------- pointnet: 64 edges x 256 ch per CTA, f16 2-product, cp.async W-hi -------
#define OFF_AH 0
#define OFF_WH 9216
#define OFF_WL 46080
#define OFF_DST 82944
#define PN_SMEM 83456
#define TILES_PER_G 6250

__global__ __launch_bounds__(256, 2)
void pointnet_mma(const float* __restrict__ b20, const float* __restrict__ b21) {
    extern __shared__ char AB[];
    uint32_t abu = smem_u32(AB);
    int tid = threadIdx.x, lane = tid & 31, wid = tid >> 5;
    int g = (blockIdx.x >= TILES_PER_G) ? 1 : 0;
    int e0 = (blockIdx.x - g*TILES_PER_G) * 64;
    const float* __restrict__ b2 = g ? b21 : b20;
    int* s_dst = (int*)(AB + OFF_DST);
    if (tid < 64) s_dst[tid] = g_sdst[g][e0 + tid];

    int ge = tid >> 2, kq = (tid & 3) * 16;
    int esrc = g_ssrc[g][e0 + ge] * 256;
    int edst = g_sdst[g][e0 + ge] * 256;
    const unsigned short* __restrict__ Aa = g_a16[g];
    const unsigned short* __restrict__ Cc = g_c16[g];

    int eg = wid >> 2, cg = wid & 3;
    int qrow = lane >> 2;
    int qc = (lane & 3) * 2;

    uint32_t aH = abu + OFF_AH + (uint32_t)(eg*32 + (lane & 15))*144 + (lane >> 4)*16;
    uint32_t bH = abu + OFF_WH +
        (uint32_t)(cg*64 + (lane >> 4)*8 + (lane & 7))*144 + ((lane >> 3) & 1)*16;
    uint32_t bL = bH + (OFF_WL - OFF_WH);

    float acc[2][8][4];
#pragma unroll
    for (int mt = 0; mt < 2; mt++)
#pragma unroll
        for (int nt = 0; nt < 8; nt++)
#pragma unroll
            for (int j = 0; j < 4; j++) acc[mt][nt][j] = 0.f;

    for (int ck = 0; ck < 4; ck++) {
        // ---- W hi via cp.async (overlaps with gather below) ----
        {
            const char* gh = (const char*)(g_w2h[g] + ck*16384);
#pragma unroll
            for (int i = 0; i < 8; i++) {
                int idx = tid + i*256;
                int row = idx >> 3, q = idx & 7;
                cpasync16(abu + OFF_WH + (uint32_t)row*144 + q*16, gh + idx*16);
            }
            CP_COMMIT();
        }
        // ---- gather f16 a/c, h = relu(a-c) in f16x2 ----
        {
            int k0 = ck*64 + kq;
            const uint4* pa = (const uint4*)(Aa + esrc + k0);
            const uint4* pc = (const uint4*)(Cc + edst + k0);
            uint4 a0 = pa[0], a1 = pa[1];
            uint4 c0 = pc[0], c1 = pc[1];
            uint4 o0, o1;
            o0.x = hsubrelu2(a0.x, c0.x); o0.y = hsubrelu2(a0.y, c0.y);
            o0.z = hsubrelu2(a0.z, c0.z); o0.w = hsubrelu2(a0.w, c0.w);
            o1.x = hsubrelu2(a1.x, c1.x); o1.y = hsubrelu2(a1.y, c1.y);
            o1.z = hsubrelu2(a1.z, c1.z); o1.w = hsubrelu2(a1.w, c1.w);
            char* ph = AB + OFF_AH + (tid >> 2)*144 + kq*2;
            *(uint4*)ph        = o0;
            *(uint4*)(ph + 16) = o1;
        }
        // ---- W lo: e5m2 load + expand ----
        {
            const uint4* gl8 = (const uint4*)(g_w2l8[g] + ck*16384);
#pragma unroll
            for (int i = 0; i < 4; i++) {
                int row = (tid >> 2) + i*64, part = tid & 3;
                uint4 s4 = gl8[row*4 + part];
                uint32_t s[4] = {s4.x, s4.y, s4.z, s4.w};
                uint32_t o[8];
#pragma unroll
                for (int j = 0; j < 4; j++) {
                    o[2*j]   = hmul2c(prmt0(s[j], 0x1404u));
                    o[2*j+1] = hmul2c(prmt0(s[j], 0x3424u));
                }
                char* dst = AB + OFF_WL + row*144 + part*32;
                *(uint4*)dst        = make_uint4(o[0], o[1], o[2], o[3]);
                *(uint4*)(dst + 16) = make_uint4(o[4], o[5], o[6], o[7]);
            }
        }
        CP_WAIT0();
        __syncthreads();

        // ---- MMA: 2 f16 products ----
#pragma unroll
        for (int kk = 0; kk < 4; kk++) {
            uint32_t ko = kk*32;
            uint32_t bh[4][4], bl[4][4];
#pragma unroll
            for (int p = 0; p < 4; p++) {
                ldsm4(bh[p], bH + p*(16*144) + ko);
                ldsm4(bl[p], bL + p*(16*144) + ko);
            }
#pragma unroll
            for (int mt = 0; mt < 2; mt++) {
                uint32_t ah[4];
                ldsm4(ah, aH + mt*(16*144) + ko);
#pragma unroll
                for (int p = 0; p < 4; p++) {
                    mma_f16f32(acc[mt][2*p],   ah, bh[p][0], bh[p][1]);
                    mma_f16f32(acc[mt][2*p+1], ah, bh[p][2], bh[p][3]);
                    mma_f16f32(acc[mt][2*p],   ah, bl[p][0], bl[p][1]);
                    mma_f16f32(acc[mt][2*p+1], ah, bl[p][2], bl[p][3]);
                }
            }
        }
        __syncthreads();
    }

    float* buf = (float*)AB;
#pragma unroll
    for (int mt = 0; mt < 2; mt++) {
        int row = eg*32 + mt*16 + qrow;
#pragma unroll
        for (int nt = 0; nt < 8; nt++) {
            int col = cg*64 + nt*8 + qc;
            buf[row*257 + col]       = acc[mt][nt][0];
            buf[row*257 + col + 1]   = acc[mt][nt][1];
            buf[(row+8)*257 + col]   = acc[mt][nt][2];
            buf[(row+8)*257 + col+1] = acc[mt][nt][3];
        }
    }
    __syncthreads();
    {
        unsigned* __restrict__ seg = &g_segout[g][0];
        int gch = tid;
        float bias = b2[gch];
        int cur = s_dst[0];
        float mx = buf[gch];
        for (int q = 1; q < 64; q++) {
            int d = s_dst[q];
            float v = buf[q*257 + gch];
            if (d != cur) {
                atomicMax(&seg[cur*256 + gch], fmap(mx + bias));
                cur = d; mx = v;
            } else mx = fmaxf(mx, v);
        }
        atomicMax(&seg[cur*256 + gch], fmap(mx + bias));
    }
}

// ------- xw via HMMA: [NN,512]@[512,128] per graph, 3-term bf16, cp.async W -------
#define XOFF_AH 0
#define XOFF_AL 18432
#define XOFF_WH 36864
#define XOFF_WL 55296
#define XW_SMEM 73728
#define XW_TILES 157

__global__ __launch_bounds__(256, 2)
void xw_mma() {
    extern __shared__ char AB[];
    uint32_t abu = smem_u32(AB);
    int tid = threadIdx.x, lane = tid & 31, wid = tid >> 5;
    int g = (blockIdx.x >= XW_TILES) ? 1 : 0;
    int row0 = (blockIdx.x - g*XW_TILES) * 128;

    int grow = tid >> 1, kh = (tid & 1) * 32;
    int ar = row0 + grow; if (ar > NN-1) ar = NN-1;

    int eg = wid >> 1, cg = wid & 1;
    int qrow = lane >> 2;
    int qc = (lane & 3) * 2;

    uint32_t aH = abu + XOFF_AH + (uint32_t)(eg*32 + (lane & 15))*144 + (lane >> 4)*16;
    uint32_t aL = aH + (XOFF_AL - XOFF_AH);
    uint32_t bH = abu + XOFF_WH +
        (uint32_t)(cg*64 + (lane >> 4)*8 + (lane & 7))*144 + ((lane >> 3) & 1)*16;
    uint32_t bL = bH + (XOFF_WL - XOFF_WH);

    float acc[2][8][4];
#pragma unroll
    for (int mt = 0; mt < 2; mt++)
#pragma unroll
        for (int nt = 0; nt < 8; nt++)
#pragma unroll
            for (int j = 0; j < 4; j++) acc[mt][nt][j] = 0.f;

    for (int ck = 0; ck < 8; ck++) {
        // W hi+lo via cp.async, overlapped with A decode
        {
            const char* gh = (const char*)(g_gwh[g] + ck*8192);
            const char* gl = (const char*)(g_gwl[g] + ck*8192);
#pragma unroll
            for (int i = 0; i < 4; i++) {
                int idx = tid + i*256;
                int row = idx >> 3, q = idx & 7;
                cpasync16(abu + XOFF_WH + (uint32_t)row*144 + q*16, gh + idx*16);
                cpasync16(abu + XOFF_WL + (uint32_t)row*144 + q*16, gl + idx*16);
            }
            CP_COMMIT();
        }
        {
            int kbase = ck*64 + kh;
            const unsigned* sp = (kbase < 256) ? &g_segout[0][ar*256 + kbase]
                                               : &g_segout[1][ar*256 + kbase - 256];
            char* ph = AB + XOFF_AH + grow*144 + kh*2;
            char* pl = AB + XOFF_AL + grow*144 + kh*2;
#pragma unroll
            for (int q = 0; q < 8; q++) {
                uint4 u = *(const uint4*)(sp + q*4);
                float h0 = (u.x > 0x80000000u) ? __uint_as_float(u.x ^ 0x80000000u) : 0.f;
                float h1 = (u.y > 0x80000000u) ? __uint_as_float(u.y ^ 0x80000000u) : 0.f;
                float h2 = (u.z > 0x80000000u) ? __uint_as_float(u.z ^ 0x80000000u) : 0.f;
                float h3 = (u.w > 0x80000000u) ? __uint_as_float(u.w ^ 0x80000000u) : 0.f;
                uint32_t hi0, hi1, lo0, lo1;
                bf16split(h0, h1, hi0, lo0);
                bf16split(h2, h3, hi1, lo1);
                *(uint32_t*)(ph + q*8)     = hi0;
                *(uint32_t*)(ph + q*8 + 4) = hi1;
                *(uint32_t*)(pl + q*8)     = lo0;
                *(uint32_t*)(pl + q*8 + 4) = lo1;
            }
        }
        CP_WAIT0();
        __syncthreads();

#pragma unroll
        for (int kk = 0; kk < 4; kk++) {
            uint32_t ko = kk*32;
            uint32_t bh[4][4], bl[4][4];
#pragma unroll
            for (int p = 0; p < 4; p++) {
                ldsm4(bh[p], bH + p*(16*144) + ko);
                ldsm4(bl[p], bL + p*(16*144) + ko);
            }
#pragma unroll
            for (int mt = 0; mt < 2; mt++) {
                uint32_t ah[4];
                ldsm4(ah, aH + mt*(16*144) + ko);
#pragma unroll
                for (int p = 0; p < 4; p++) {
                    mma_bf16(acc[mt][2*p],   ah, bh[p][0], bh[p][1]);
                    mma_bf16(acc[mt][2*p+1], ah, bh[p][2], bh[p][3]);
                }
            }
#pragma unroll
            for (int mt = 0; mt < 2; mt++) {
                uint32_t al[4];
                ldsm4(al, aL + mt*(16*144) + ko);
#pragma unroll
                for (int p = 0; p < 4; p++) {
                    mma_bf16(acc[mt][2*p],   al, bh[p][0], bh[p][1]);
                    mma_bf16(acc[mt][2*p+1], al, bh[p][2], bh[p][3]);
                }
            }
#pragma unroll
            for (int mt = 0; mt < 2; mt++) {
                uint32_t ah2[4];
                ldsm4(ah2, aH + mt*(16*144) + ko);
#pragma unroll
                for (int p = 0; p < 4; p++) {
                    mma_bf16(acc[mt][2*p],   ah2, bl[p][0], bl[p][1]);
                    mma_bf16(acc[mt][2*p+1], ah2, bl[p][2], bl[p][3]);
                }
            }
        }
        __syncthreads();
    }

    float* __restrict__ xw = g_xw[g];
#pragma unroll
    for (int mt = 0; mt < 2; mt++) {
        int r0 = row0 + eg*32 + mt*16 + qrow;
#pragma unroll
        for (int nt = 0; nt < 8; nt++) {
            int col = cg*64 + nt*8 + qc;
            if (r0 < NN)
                *(float2*)(xw + r0*128 + col) = make_float2(acc[mt][nt][0], acc[mt][nt][1]);
            if (r0 + 8 < NN)
                *(float2*)(xw + (r0+8)*128 + col) = make_float2(acc[mt][nt][2], acc[mt][nt][3]);
        }
    }
}

// ------- agg: one block per node, both graphs, float2 channels -------
__global__ void agg_paired(const float* __restrict__ gb0, const float* __restrict__ gb1) {
    int i = blockIdx.x;
    int t = threadIdx.x;
    int g = t >> 6;
    int ch = (t & 63) * 2;
    const float* __restrict__ xw = g_xw[g];
    const float* __restrict__ bias = g ? gb1 : gb0;
    float di = g_dinv[g][i];
    int beg = g_offs[g][i], end = g_offs[g][i+1];
    float ax = 0.f, ay = 0.f;
    for (int e = beg; e < end; e++) {
        int s = g_ssrc[g][e];
        float2 v = *(const float2*)(xw + s*128 + ch);
        float dv = g_dinv[g][s];
        ax += v.x * dv; ay += v.y * dv;
    }
    float2 self = *(const float2*)(xw + i*128 + ch);
    float d2 = di*di;
    float vx = di*ax + self.x*d2 + bias[ch];
    float vy = di*ay + self.y*d2 + bias[ch+1];
    *(float2*)(&g_h2[i*256 + g*128 + ch]) = make_float2(fmaxf(vx, 0.f), fmaxf(vy, 0.f));
}

__global__ __launch_bounds__(256)
void c3cls_kernel(const float* __restrict__ Wc, const float* __restrict__ bc,
                  const float* __restrict__ clsW) {
    __shared__ float s_a[64*16];
    __shared__ float4 s_b[16*32];
    __shared__ float red[256];
    int tid = threadIdx.x, tx = tid & 31, ty = tid >> 5;
    int row0 = blockIdx.x * 64;
    float acc[8][4];
#pragma unroll
    for (int i = 0; i < 8; i++)
#pragma unroll
        for (int j = 0; j < 4; j++) acc[i][j] = 0.f;
    int lr = tid >> 2, lk = (tid & 3) * 4;
    int ar = row0 + lr; if (ar > NN-1) ar = NN-1;
    const float4* B4 = (const float4*)Wc;
    for (int k0 = 0; k0 < 256; k0 += 16) {
        float4 av = *(const float4*)(g_h2 + ar*256 + k0 + lk);
        float4 bv[2];
#pragma unroll
        for (int q = 0; q < 2; q++) {
            int idx = tid + q*256;
            bv[q] = B4[(k0 + (idx >> 5))*32 + (idx & 31)];
        }
        __syncthreads();
        *(float4*)(s_a + lr*16 + lk) = av;
#pragma unroll
        for (int q = 0; q < 2; q++) s_b[tid + q*256] = bv[q];
        __syncthreads();
#pragma unroll
        for (int kk = 0; kk < 16; kk++) {
            float4 b = s_b[kk*32 + tx];
#pragma unroll
            for (int i = 0; i < 8; i++) {
                float a = s_a[(ty*8 + i)*16 + kk];
                acc[i][0] += a*b.x; acc[i][1] += a*b.y;
                acc[i][2] += a*b.z; acc[i][3] += a*b.w;
            }
        }
    }
    float sum0 = 0.f, sum1 = 0.f, sum2 = 0.f;
#pragma unroll
    for (int i = 0; i < 8; i++) {
        int r = row0 + ty*8 + i;
        if (r < NN) {
#pragma unroll
            for (int jj = 0; jj < 4; jj++) {
                float v = fmaxf(acc[i][jj] + bc[tx*4 + jj], 0.f);
                const float* w = clsW + (r*128 + tx*4 + jj)*3;
                sum0 += v*w[0]; sum1 += v*w[1]; sum2 += v*w[2];
            }
        }
    }
    float sums[3] = {sum0, sum1, sum2};
#pragma unroll
    for (int r3 = 0; r3 < 3; r3++) {
        red[tid] = sums[r3];
        __syncthreads();
        for (int s = 128; s > 0; s >>= 1) {
            if (tid < s) red[tid] += red[tid + s];
            __syncthreads();
        }
        if (tid == 0) g_partial[blockIdx.x*3 + r3] = red[0];
        __syncthreads();
    }
}

__global__ void final_kernel(const float* __restrict__ clsb, float* __restrict__ out, int nblk) {
    int r = threadIdx.x;
    if (r < 3) {
        double s = (double)clsb[r];
        for (int i = 0; i < nblk; i++) s += (double)g_partial[i*3 + r];
        out[r] = (float)s;
    }
}

extern "C" void kernel_launch(void* const* d_in, const int* in_sizes, int n_in,
                              void* d_out, int out_size) {
    const float *pos[2]={0,0}, *W1[2]={0,0}, *b1[2]={0,0}, *W2[2]={0,0}, *b2[2]={0,0};
    const float *gW[2]={0,0}, *gb[2]={0,0}, *cW=0, *cb=0, *clsW=0, *clsb=0;
    const int *ei[2]={0,0};
    int npos=0, nei=0, nw1=0, n256=0, n64k=0, n128=0;
    for (int i = 0; i < n_in; i++) {
        int sz = in_sizes[i];
        const float* f = (const float*)d_in[i];
        if (sz == 3*NN)            { if (npos<2) pos[npos++] = f; }
        else if (sz == 2*NE)       { if (nei<2)  ei[nei++] = (const int*)d_in[i]; }
        else if (sz == 6*H)        { if (nw1<2)  W1[nw1++] = f; }
        else if (sz == H)          { int j=n256++; if(j==0)b1[0]=f; else if(j==1)b2[0]=f;
                                     else if(j==2)b1[1]=f; else if(j==3)b2[1]=f; }
        else if (sz == H*H)        { int j=n64k++; if(j<2) W2[j]=f; else if(j<4) gW[j-2]=f; }
        else if (sz == H/2)        { int j=n128++; if(j<2) gb[j]=f; else cb=f; }
        else if (sz == H*(H/2))    { cW = f; }
        else if (sz == NN*(H/2)*3) { clsW = f; }
        else if (sz == 3)          { clsb = f; }
    }

    static bool attr_done = false;
    if (!attr_done) {
        cudaFuncSetAttribute(pointnet_mma, cudaFuncAttributeMaxDynamicSharedMemorySize, PN_SMEM);
        cudaFuncSetAttribute(xw_mma, cudaFuncAttributeMaxDynamicSharedMemorySize, XW_SMEM);
        attr_done = true;
    }

    w2prep_fused<<<512, 256>>>(W2[0], W2[1]);          // clears deg
    gwprep_fused<<<512, 256>>>(gW[0], gW[1]);
    uv_fused<<<2*NN, 256>>>(pos[0], pos[1], W1[0], W1[1], b1[0], b1[1], ei[0], ei[1]); // + deg atomics
    scan_a<<<160, 256>>>();
    scan_b<<<1, 256>>>();
    scan_c<<<160, 256>>>();
    fill_fused<<<(2*NE + 255)/256, 256>>>(ei[0], ei[1]);
    pointnet_mma<<<2*TILES_PER_G, 256, PN_SMEM>>>(b2[0], b2[1]);
    xw_mma<<<2*XW_TILES, 256, XW_SMEM>>>();
    agg_paired<<<NN, 128>>>(gb[0], gb[1]);
    int nblk = (NN + 63)/64;
    c3cls_kernel<<<nblk, 256>>>(cW, cb, clsW);
    final_kernel<<<1, 32>>>(clsb, (float*)d_out, nblk);
}